// round 4
// baseline (speedup 1.0000x reference)
#include <cuda_runtime.h>
#include <cstdint>

#define D_MODEL 4096
#define E3      12288
#define NHEADS  32
#define HDIM    128
#define BATCH   2
#define SEQ     2048
#define ROWS    (BATCH*SEQ)   /* 4096 */
#define CLIP_V  8.0f
#define LN_EPS  1e-5f

// Scratch (allocation-free rule: __device__ globals)
__device__ float g_qkv[(size_t)ROWS * E3];       // [4096][12288] post-GEMM1 (q|k|v)
__device__ float g_attn[(size_t)ROWS * D_MODEL]; // [4096][4096]  attention output

// ===========================================================================
// mma.sync tf32 helpers (sm_80+)
// ===========================================================================
__device__ __forceinline__ uint32_t f2tf(float f) {
    uint32_t r;
    asm("cvt.rna.tf32.f32 %0, %1;" : "=r"(r) : "f"(f));
    return r;
}

__device__ __forceinline__ void mma_tf32(float* d, const uint32_t* a, const uint32_t* b) {
    asm volatile(
        "mma.sync.aligned.m16n8k8.row.col.f32.tf32.tf32.f32 "
        "{%0,%1,%2,%3}, {%4,%5,%6,%7}, {%8,%9}, {%0,%1,%2,%3};"
        : "+f"(d[0]), "+f"(d[1]), "+f"(d[2]), "+f"(d[3])
        : "r"(a[0]), "r"(a[1]), "r"(a[2]), "r"(a[3]), "r"(b[0]), "r"(b[1]));
}

// ===========================================================================
// TF32 tensor-core GEMM (unchanged from R3): C[m][n] = sum_k A[m][k]*W[n][k]
// ===========================================================================
#define LDP 36
#define TILE_U32 (128*LDP)
#define GEMM_SMEM (4 * TILE_U32 * 4)

template<bool DO_CLIP>
__global__ __launch_bounds__(256)
void gemm_mma(const float* __restrict__ A, const float* __restrict__ W,
              float* __restrict__ C, int Ntot, int K) {
    extern __shared__ uint32_t sm[];
    uint32_t* As[2] = { sm,            sm + 2 * TILE_U32 };
    uint32_t* Bs[2] = { sm + TILE_U32, sm + 3 * TILE_U32 };

    const int tid  = threadIdx.x;
    const int lane = tid & 31;
    const int warp = tid >> 5;
    const int wm0  = (warp >> 2) << 6;
    const int wn0  = (warp & 3) << 5;
    const int m0 = blockIdx.y << 7, n0 = blockIdx.x << 7;

    const float* Ab = A + (size_t)m0 * K;
    const float* Wb = W + (size_t)n0 * K;

    const int lrow = tid >> 3;
    const int lcg  = tid & 7;

    float acc[4][4][4];
#pragma unroll
    for (int a = 0; a < 4; a++)
#pragma unroll
        for (int b = 0; b < 4; b++)
#pragma unroll
            for (int c = 0; c < 4; c++) acc[a][b][c] = 0.f;

    const int NS = K >> 5;
    float4 pa[4], pb[4];

#pragma unroll
    for (int i = 0; i < 4; i++) {
        int row = lrow + (i << 5);
        pa[i] = *(const float4*)(Ab + (size_t)row * K + lcg * 4);
        pb[i] = *(const float4*)(Wb + (size_t)row * K + lcg * 4);
    }
#pragma unroll
    for (int i = 0; i < 4; i++) {
        int row = lrow + (i << 5);
        uint32_t* pda = As[0] + row * LDP + lcg * 4;
        pda[0] = f2tf(pa[i].x); pda[1] = f2tf(pa[i].y);
        pda[2] = f2tf(pa[i].z); pda[3] = f2tf(pa[i].w);
        uint32_t* pdb = Bs[0] + row * LDP + lcg * 4;
        pdb[0] = f2tf(pb[i].x); pdb[1] = f2tf(pb[i].y);
        pdb[2] = f2tf(pb[i].z); pdb[3] = f2tf(pb[i].w);
    }
    __syncthreads();

    for (int s = 0; s < NS; s++) {
        if (s + 1 < NS) {
            const int k0 = (s + 1) << 5;
#pragma unroll
            for (int i = 0; i < 4; i++) {
                int row = lrow + (i << 5);
                pa[i] = *(const float4*)(Ab + (size_t)row * K + k0 + lcg * 4);
                pb[i] = *(const float4*)(Wb + (size_t)row * K + k0 + lcg * 4);
            }
        }

        const uint32_t* Ac = As[s & 1];
        const uint32_t* Bc = Bs[s & 1];
#pragma unroll
        for (int kk = 0; kk < 4; kk++) {
            const int kb = kk << 3;
            uint32_t af[4][4], bf[4][2];
#pragma unroll
            for (int mt = 0; mt < 4; mt++) {
                int r = wm0 + (mt << 4) + (lane >> 2);
                int c = kb + (lane & 3);
                af[mt][0] = Ac[r * LDP + c];
                af[mt][1] = Ac[(r + 8) * LDP + c];
                af[mt][2] = Ac[r * LDP + c + 4];
                af[mt][3] = Ac[(r + 8) * LDP + c + 4];
            }
#pragma unroll
            for (int nt = 0; nt < 4; nt++) {
                int n = wn0 + (nt << 3) + (lane >> 2);
                int c = kb + (lane & 3);
                bf[nt][0] = Bc[n * LDP + c];
                bf[nt][1] = Bc[n * LDP + c + 4];
            }
#pragma unroll
            for (int mt = 0; mt < 4; mt++)
#pragma unroll
                for (int nt = 0; nt < 4; nt++)
                    mma_tf32(acc[mt][nt], af[mt], bf[nt]);
        }

        if (s + 1 < NS) {
            uint32_t* Ad = As[(s + 1) & 1];
            uint32_t* Bd = Bs[(s + 1) & 1];
#pragma unroll
            for (int i = 0; i < 4; i++) {
                int row = lrow + (i << 5);
                uint32_t* pda = Ad + row * LDP + lcg * 4;
                pda[0] = f2tf(pa[i].x); pda[1] = f2tf(pa[i].y);
                pda[2] = f2tf(pa[i].z); pda[3] = f2tf(pa[i].w);
                uint32_t* pdb = Bd + row * LDP + lcg * 4;
                pdb[0] = f2tf(pb[i].x); pdb[1] = f2tf(pb[i].y);
                pdb[2] = f2tf(pb[i].z); pdb[3] = f2tf(pb[i].w);
            }
            __syncthreads();
        }
    }

#pragma unroll
    for (int mt = 0; mt < 4; mt++) {
#pragma unroll
        for (int nt = 0; nt < 4; nt++) {
            int row = m0 + wm0 + (mt << 4) + (lane >> 2);
            int col = n0 + wn0 + (nt << 3) + ((lane & 3) << 1);
            float2 v0 = make_float2(acc[mt][nt][0], acc[mt][nt][1]);
            float2 v1 = make_float2(acc[mt][nt][2], acc[mt][nt][3]);
            if (DO_CLIP) {
                v0.x = fminf(fmaxf(v0.x, -CLIP_V), CLIP_V);
                v0.y = fminf(fmaxf(v0.y, -CLIP_V), CLIP_V);
                v1.x = fminf(fmaxf(v1.x, -CLIP_V), CLIP_V);
                v1.y = fminf(fmaxf(v1.y, -CLIP_V), CLIP_V);
            }
            *(float2*)(C + (size_t)row * Ntot + col) = v0;
            *(float2*)(C + (size_t)(row + 8) * Ntot + col) = v1;
        }
    }
}

// ---------------------------------------------------------------------------
// LayerNorm (unchanged)
// ---------------------------------------------------------------------------
__global__ __launch_bounds__(256)
void ln_kernel(float* __restrict__ base, int col_off,
               const float* __restrict__ w, const float* __restrict__ b) {
    __shared__ float red0[8], red1[8];
    __shared__ float mu_s, inv_s;
    float* x = base + (size_t)blockIdx.x * E3 + col_off;
    const int tid = threadIdx.x;

    float s = 0.f, s2 = 0.f;
    for (int i = tid; i < D_MODEL; i += 256) {
        float v = x[i]; s += v; s2 += v * v;
    }
#pragma unroll
    for (int o = 16; o; o >>= 1) {
        s  += __shfl_down_sync(0xffffffffu, s,  o);
        s2 += __shfl_down_sync(0xffffffffu, s2, o);
    }
    if ((tid & 31) == 0) { red0[tid >> 5] = s; red1[tid >> 5] = s2; }
    __syncthreads();
    if (tid == 0) {
        float S = 0.f, S2 = 0.f;
#pragma unroll
        for (int i = 0; i < 8; i++) { S += red0[i]; S2 += red1[i]; }
        float mu = S * (1.f / D_MODEL);
        float var = S2 * (1.f / D_MODEL) - mu * mu;
        mu_s = mu;
        inv_s = rsqrtf(var + LN_EPS);
    }
    __syncthreads();
    const float mu = mu_s, inv = inv_s;
    for (int i = tid; i < D_MODEL; i += 256) {
        x[i] = (x[i] - mu) * inv * w[i] + b[i];
    }
}

// ---------------------------------------------------------------------------
// Flash attention v2 (fp32, causal, ALiBi) — vectorized LDS.128 everywhere,
// 256-thread softmax. grid = (S/64, H, B), 256 threads.
// ---------------------------------------------------------------------------
#define KSTR 132   /* padded K-tile row stride (floats), conflict-free float4 */
#define PSTR 68    /* P-tile row stride */

__global__ __launch_bounds__(256)
void attn_kernel(const float* __restrict__ qkv, float* __restrict__ outp) {
    extern __shared__ float smf[];
    float* Qs   = smf;                 // 64*128
    float* Ks   = Qs + 64*128;         // 64*132
    float* Vs   = Ks + 64*KSTR;        // 64*128
    float* Ps   = Vs + 64*128;         // 64*68
    float* rowm = Ps + 64*PSTR;        // 64
    float* rowl = rowm + 64;           // 64
    float* rowr = rowl + 64;           // 64

    const int qt = blockIdx.x, h = blockIdx.y, b = blockIdx.z;
    const int tid = threadIdx.x;
    const int tx = tid & 15, ty = tid >> 4;
    const float scale = 0.08838834764831845f;            // 1/sqrt(128)
    const float slope = exp2f(-0.25f * (float)(h + 1));  // ALiBi, H == next_p2
    const size_t rowbase = (size_t)b * SEQ;

    // Load + pre-scale Q tile (float4)
    for (int i = tid; i < 64 * HDIM / 4; i += 256) {
        int r = i >> 5; int c = (i & 31) << 2;
        float4 v = *(const float4*)(qkv + (rowbase + qt*64 + r) * E3 + h*HDIM + c);
        v.x *= scale; v.y *= scale; v.z *= scale; v.w *= scale;
        *(float4*)(Qs + r*HDIM + c) = v;
    }
    if (tid < 64) { rowm[tid] = -1e30f; rowl[tid] = 0.f; }
    float o[4][8];
#pragma unroll
    for (int i = 0; i < 4; i++)
#pragma unroll
        for (int c = 0; c < 8; c++) o[i][c] = 0.f;
    __syncthreads();

    for (int kt = 0; kt <= qt; kt++) {
        // Load K (stride 132) and V tiles, float4 stores
        for (int i = tid; i < 64 * HDIM / 4; i += 256) {
            int r = i >> 5; int c = (i & 31) << 2;
            const float* kp = qkv + (rowbase + kt*64 + r) * E3 + D_MODEL + h*HDIM + c;
            *(float4*)(Ks + r*KSTR + c) = *(const float4*)kp;
            *(float4*)(Vs + r*HDIM + c) = *(const float4*)(kp + D_MODEL);
        }
        __syncthreads();

        // S = (Q*scale) K^T  — float4 smem loads, kb step 4
        float sacc[4][4] = {};
#pragma unroll 4
        for (int kb = 0; kb < HDIM; kb += 4) {
            float4 a4[4], b4[4];
#pragma unroll
            for (int i = 0; i < 4; i++) a4[i] = *(const float4*)(Qs + (ty*4+i)*HDIM + kb);
#pragma unroll
            for (int j = 0; j < 4; j++) b4[j] = *(const float4*)(Ks + (tx*4+j)*KSTR + kb);
#pragma unroll
            for (int i = 0; i < 4; i++)
#pragma unroll
                for (int j = 0; j < 4; j++) {
                    sacc[i][j] = fmaf(a4[i].x, b4[j].x, sacc[i][j]);
                    sacc[i][j] = fmaf(a4[i].y, b4[j].y, sacc[i][j]);
                    sacc[i][j] = fmaf(a4[i].z, b4[j].z, sacc[i][j]);
                    sacc[i][j] = fmaf(a4[i].w, b4[j].w, sacc[i][j]);
                }
        }

        // ALiBi + causal mask -> Ps (float4 stores)
        const int qb = qt*64 + ty*4, kb0 = kt*64 + tx*4;
#pragma unroll
        for (int i = 0; i < 4; i++) {
            int qi = qb + i;
            float v[4];
#pragma unroll
            for (int j = 0; j < 4; j++) {
                int kj = kb0 + j;
                float s = sacc[i][j] + slope * (float)(kj - qi);
                v[j] = (kj > qi) ? -1e30f : s;
            }
            *(float4*)(Ps + (ty*4+i)*PSTR + tx*4) =
                make_float4(v[0], v[1], v[2], v[3]);
        }
        __syncthreads();

        // Online softmax — 256 threads, 4 lanes/row, 16 cols each
        {
            const int row = tid >> 2;
            const int q4  = tid & 3;
            float4* p4 = (float4*)(Ps + row*PSTR + q4*16);
            float m_old = rowm[row];
            float4 x0 = p4[0], x1 = p4[1], x2 = p4[2], x3 = p4[3];
            float mx = fmaxf(fmaxf(fmaxf(x0.x, x0.y), fmaxf(x0.z, x0.w)),
                             fmaxf(fmaxf(x1.x, x1.y), fmaxf(x1.z, x1.w)));
            mx = fmaxf(mx, fmaxf(fmaxf(fmaxf(x2.x, x2.y), fmaxf(x2.z, x2.w)),
                                 fmaxf(fmaxf(x3.x, x3.y), fmaxf(x3.z, x3.w))));
            mx = fmaxf(mx, __shfl_xor_sync(0xffffffffu, mx, 1));
            mx = fmaxf(mx, __shfl_xor_sync(0xffffffffu, mx, 2));
            mx = fmaxf(mx, m_old);
            x0.x = __expf(x0.x - mx); x0.y = __expf(x0.y - mx);
            x0.z = __expf(x0.z - mx); x0.w = __expf(x0.w - mx);
            x1.x = __expf(x1.x - mx); x1.y = __expf(x1.y - mx);
            x1.z = __expf(x1.z - mx); x1.w = __expf(x1.w - mx);
            x2.x = __expf(x2.x - mx); x2.y = __expf(x2.y - mx);
            x2.z = __expf(x2.z - mx); x2.w = __expf(x2.w - mx);
            x3.x = __expf(x3.x - mx); x3.y = __expf(x3.y - mx);
            x3.z = __expf(x3.z - mx); x3.w = __expf(x3.w - mx);
            float sum = (x0.x + x0.y + x0.z + x0.w) + (x1.x + x1.y + x1.z + x1.w)
                      + (x2.x + x2.y + x2.z + x2.w) + (x3.x + x3.y + x3.z + x3.w);
            p4[0] = x0; p4[1] = x1; p4[2] = x2; p4[3] = x3;
            sum += __shfl_xor_sync(0xffffffffu, sum, 1);
            sum += __shfl_xor_sync(0xffffffffu, sum, 2);
            if (q4 == 0) {
                float r_ = __expf(m_old - mx);
                rowm[row] = mx;
                rowl[row] = rowl[row] * r_ + sum;
                rowr[row] = r_;
            }
        }
        __syncthreads();

        // Rescale O, accumulate P@V — float4 P loads, kb2 step 4
        float rr[4];
#pragma unroll
        for (int i = 0; i < 4; i++) rr[i] = rowr[ty*4+i];
#pragma unroll
        for (int i = 0; i < 4; i++)
#pragma unroll
            for (int c = 0; c < 8; c++) o[i][c] *= rr[i];
#pragma unroll 2
        for (int kb2 = 0; kb2 < 64; kb2 += 4) {
            float pv[4][4];
#pragma unroll
            for (int i = 0; i < 4; i++) {
                float4 p = *(const float4*)(Ps + (ty*4+i)*PSTR + kb2);
                pv[i][0] = p.x; pv[i][1] = p.y; pv[i][2] = p.z; pv[i][3] = p.w;
            }
#pragma unroll
            for (int t = 0; t < 4; t++) {
                float4 v0 = *(const float4*)(Vs + (kb2+t)*HDIM + tx*8);
                float4 v1 = *(const float4*)(Vs + (kb2+t)*HDIM + tx*8 + 4);
#pragma unroll
                for (int i = 0; i < 4; i++) {
                    float p = pv[i][t];
                    o[i][0] = fmaf(p, v0.x, o[i][0]);
                    o[i][1] = fmaf(p, v0.y, o[i][1]);
                    o[i][2] = fmaf(p, v0.z, o[i][2]);
                    o[i][3] = fmaf(p, v0.w, o[i][3]);
                    o[i][4] = fmaf(p, v1.x, o[i][4]);
                    o[i][5] = fmaf(p, v1.y, o[i][5]);
                    o[i][6] = fmaf(p, v1.z, o[i][6]);
                    o[i][7] = fmaf(p, v1.w, o[i][7]);
                }
            }
        }
        __syncthreads();
    }

    // Normalize and write
#pragma unroll
    for (int i = 0; i < 4; i++) {
        float inv = 1.f / rowl[ty*4+i];
        float* op = outp + (rowbase + qt*64 + ty*4 + i) * (size_t)D_MODEL + h*HDIM + tx*8;
        float4 w0 = make_float4(o[i][0]*inv, o[i][1]*inv, o[i][2]*inv, o[i][3]*inv);
        float4 w1 = make_float4(o[i][4]*inv, o[i][5]*inv, o[i][6]*inv, o[i][7]*inv);
        *(float4*)op = w0;
        *(float4*)(op + 4) = w1;
    }
}

#define ATTN_SMEM ((64*128 + 64*KSTR + 64*128 + 64*PSTR + 3*64) * (int)sizeof(float))

// ---------------------------------------------------------------------------
extern "C" void kernel_launch(void* const* d_in, const int* in_sizes, int n_in,
                              void* d_out, int out_size) {
    const float* hidden = (const float*)d_in[0];
    const float* w_qkv  = (const float*)d_in[1];
    const float* q_ln_w = (const float*)d_in[2];
    const float* q_ln_b = (const float*)d_in[3];
    const float* k_ln_w = (const float*)d_in[4];
    const float* k_ln_b = (const float*)d_in[5];
    const float* w_out  = (const float*)d_in[6];
    float* out = (float*)d_out;

    float *qkv, *attn;
    cudaGetSymbolAddress((void**)&qkv, g_qkv);
    cudaGetSymbolAddress((void**)&attn, g_attn);

    cudaFuncSetAttribute(gemm_mma<true>,  cudaFuncAttributeMaxDynamicSharedMemorySize, GEMM_SMEM);
    cudaFuncSetAttribute(gemm_mma<false>, cudaFuncAttributeMaxDynamicSharedMemorySize, GEMM_SMEM);
    cudaFuncSetAttribute(attn_kernel, cudaFuncAttributeMaxDynamicSharedMemorySize, ATTN_SMEM);

    // 1) QKV projection + clip (tf32 tensor cores)
    dim3 g1(E3 / 128, ROWS / 128);
    gemm_mma<true><<<g1, 256, GEMM_SMEM>>>(hidden, w_qkv, qkv, E3, D_MODEL);

    // 2) q/k LayerNorms
    ln_kernel<<<ROWS, 256>>>(qkv, 0,       q_ln_w, q_ln_b);
    ln_kernel<<<ROWS, 256>>>(qkv, D_MODEL, k_ln_w, k_ln_b);

    // 3) Flash attention (vectorized)
    dim3 ga(SEQ / 64, NHEADS, BATCH);
    attn_kernel<<<ga, 256, ATTN_SMEM>>>(qkv, attn);

    // 4) Output projection -> d_out (tf32 tensor cores)
    dim3 g2(D_MODEL / 128, ROWS / 128);
    gemm_mma<false><<<g2, 256, GEMM_SMEM>>>(attn, w_out, out, D_MODEL, D_MODEL);
}

// round 5
// speedup vs baseline: 1.1383x; 1.1383x over previous
#include <cuda_runtime.h>
#include <cstdint>

#define D_MODEL 4096
#define E3      12288
#define NHEADS  32
#define HDIM    128
#define BATCH   2
#define SEQ     2048
#define ROWS    (BATCH*SEQ)   /* 4096 */
#define CLIP_V  8.0f
#define LN_EPS  1e-5f

// Scratch (allocation-free rule: __device__ globals)
__device__ float g_qkv[(size_t)ROWS * E3];       // [4096][12288] post-GEMM1 (q|k|v)
__device__ float g_attn[(size_t)ROWS * D_MODEL]; // [4096][4096]  attention output

// ===========================================================================
// mma.sync tf32 helpers (sm_80+)
// ===========================================================================
__device__ __forceinline__ uint32_t f2tf(float f) {
    uint32_t r;
    asm("cvt.rna.tf32.f32 %0, %1;" : "=r"(r) : "f"(f));
    return r;
}

__device__ __forceinline__ void mma_tf32(float* d, const uint32_t* a, const uint32_t* b) {
    asm volatile(
        "mma.sync.aligned.m16n8k8.row.col.f32.tf32.tf32.f32 "
        "{%0,%1,%2,%3}, {%4,%5,%6,%7}, {%8,%9}, {%0,%1,%2,%3};"
        : "+f"(d[0]), "+f"(d[1]), "+f"(d[2]), "+f"(d[3])
        : "r"(a[0]), "r"(a[1]), "r"(a[2]), "r"(a[3]), "r"(b[0]), "r"(b[1]));
}

// ===========================================================================
// TF32 tensor-core GEMM (unchanged from R3): C[m][n] = sum_k A[m][k]*W[n][k]
// ===========================================================================
#define LDP 36
#define TILE_U32 (128*LDP)
#define GEMM_SMEM (4 * TILE_U32 * 4)

template<bool DO_CLIP>
__global__ __launch_bounds__(256)
void gemm_mma(const float* __restrict__ A, const float* __restrict__ W,
              float* __restrict__ C, int Ntot, int K) {
    extern __shared__ uint32_t sm[];
    uint32_t* As[2] = { sm,            sm + 2 * TILE_U32 };
    uint32_t* Bs[2] = { sm + TILE_U32, sm + 3 * TILE_U32 };

    const int tid  = threadIdx.x;
    const int lane = tid & 31;
    const int warp = tid >> 5;
    const int wm0  = (warp >> 2) << 6;
    const int wn0  = (warp & 3) << 5;
    const int m0 = blockIdx.y << 7, n0 = blockIdx.x << 7;

    const float* Ab = A + (size_t)m0 * K;
    const float* Wb = W + (size_t)n0 * K;

    const int lrow = tid >> 3;
    const int lcg  = tid & 7;

    float acc[4][4][4];
#pragma unroll
    for (int a = 0; a < 4; a++)
#pragma unroll
        for (int b = 0; b < 4; b++)
#pragma unroll
            for (int c = 0; c < 4; c++) acc[a][b][c] = 0.f;

    const int NS = K >> 5;
    float4 pa[4], pb[4];

#pragma unroll
    for (int i = 0; i < 4; i++) {
        int row = lrow + (i << 5);
        pa[i] = *(const float4*)(Ab + (size_t)row * K + lcg * 4);
        pb[i] = *(const float4*)(Wb + (size_t)row * K + lcg * 4);
    }
#pragma unroll
    for (int i = 0; i < 4; i++) {
        int row = lrow + (i << 5);
        uint32_t* pda = As[0] + row * LDP + lcg * 4;
        pda[0] = f2tf(pa[i].x); pda[1] = f2tf(pa[i].y);
        pda[2] = f2tf(pa[i].z); pda[3] = f2tf(pa[i].w);
        uint32_t* pdb = Bs[0] + row * LDP + lcg * 4;
        pdb[0] = f2tf(pb[i].x); pdb[1] = f2tf(pb[i].y);
        pdb[2] = f2tf(pb[i].z); pdb[3] = f2tf(pb[i].w);
    }
    __syncthreads();

    for (int s = 0; s < NS; s++) {
        if (s + 1 < NS) {
            const int k0 = (s + 1) << 5;
#pragma unroll
            for (int i = 0; i < 4; i++) {
                int row = lrow + (i << 5);
                pa[i] = *(const float4*)(Ab + (size_t)row * K + k0 + lcg * 4);
                pb[i] = *(const float4*)(Wb + (size_t)row * K + k0 + lcg * 4);
            }
        }

        const uint32_t* Ac = As[s & 1];
        const uint32_t* Bc = Bs[s & 1];
#pragma unroll
        for (int kk = 0; kk < 4; kk++) {
            const int kb = kk << 3;
            uint32_t af[4][4], bf[4][2];
#pragma unroll
            for (int mt = 0; mt < 4; mt++) {
                int r = wm0 + (mt << 4) + (lane >> 2);
                int c = kb + (lane & 3);
                af[mt][0] = Ac[r * LDP + c];
                af[mt][1] = Ac[(r + 8) * LDP + c];
                af[mt][2] = Ac[r * LDP + c + 4];
                af[mt][3] = Ac[(r + 8) * LDP + c + 4];
            }
#pragma unroll
            for (int nt = 0; nt < 4; nt++) {
                int n = wn0 + (nt << 3) + (lane >> 2);
                int c = kb + (lane & 3);
                bf[nt][0] = Bc[n * LDP + c];
                bf[nt][1] = Bc[n * LDP + c + 4];
            }
#pragma unroll
            for (int mt = 0; mt < 4; mt++)
#pragma unroll
                for (int nt = 0; nt < 4; nt++)
                    mma_tf32(acc[mt][nt], af[mt], bf[nt]);
        }

        if (s + 1 < NS) {
            uint32_t* Ad = As[(s + 1) & 1];
            uint32_t* Bd = Bs[(s + 1) & 1];
#pragma unroll
            for (int i = 0; i < 4; i++) {
                int row = lrow + (i << 5);
                uint32_t* pda = Ad + row * LDP + lcg * 4;
                pda[0] = f2tf(pa[i].x); pda[1] = f2tf(pa[i].y);
                pda[2] = f2tf(pa[i].z); pda[3] = f2tf(pa[i].w);
                uint32_t* pdb = Bd + row * LDP + lcg * 4;
                pdb[0] = f2tf(pb[i].x); pdb[1] = f2tf(pb[i].y);
                pdb[2] = f2tf(pb[i].z); pdb[3] = f2tf(pb[i].w);
            }
            __syncthreads();
        }
    }

#pragma unroll
    for (int mt = 0; mt < 4; mt++) {
#pragma unroll
        for (int nt = 0; nt < 4; nt++) {
            int row = m0 + wm0 + (mt << 4) + (lane >> 2);
            int col = n0 + wn0 + (nt << 3) + ((lane & 3) << 1);
            float2 v0 = make_float2(acc[mt][nt][0], acc[mt][nt][1]);
            float2 v1 = make_float2(acc[mt][nt][2], acc[mt][nt][3]);
            if (DO_CLIP) {
                v0.x = fminf(fmaxf(v0.x, -CLIP_V), CLIP_V);
                v0.y = fminf(fmaxf(v0.y, -CLIP_V), CLIP_V);
                v1.x = fminf(fmaxf(v1.x, -CLIP_V), CLIP_V);
                v1.y = fminf(fmaxf(v1.y, -CLIP_V), CLIP_V);
            }
            *(float2*)(C + (size_t)row * Ntot + col) = v0;
            *(float2*)(C + (size_t)(row + 8) * Ntot + col) = v1;
        }
    }
}

// ---------------------------------------------------------------------------
// LayerNorm (unchanged)
// ---------------------------------------------------------------------------
__global__ __launch_bounds__(256)
void ln_kernel(float* __restrict__ base, int col_off,
               const float* __restrict__ w, const float* __restrict__ b) {
    __shared__ float red0[8], red1[8];
    __shared__ float mu_s, inv_s;
    float* x = base + (size_t)blockIdx.x * E3 + col_off;
    const int tid = threadIdx.x;

    float s = 0.f, s2 = 0.f;
    for (int i = tid; i < D_MODEL; i += 256) {
        float v = x[i]; s += v; s2 += v * v;
    }
#pragma unroll
    for (int o = 16; o; o >>= 1) {
        s  += __shfl_down_sync(0xffffffffu, s,  o);
        s2 += __shfl_down_sync(0xffffffffu, s2, o);
    }
    if ((tid & 31) == 0) { red0[tid >> 5] = s; red1[tid >> 5] = s2; }
    __syncthreads();
    if (tid == 0) {
        float S = 0.f, S2 = 0.f;
#pragma unroll
        for (int i = 0; i < 8; i++) { S += red0[i]; S2 += red1[i]; }
        float mu = S * (1.f / D_MODEL);
        float var = S2 * (1.f / D_MODEL) - mu * mu;
        mu_s = mu;
        inv_s = rsqrtf(var + LN_EPS);
    }
    __syncthreads();
    const float mu = mu_s, inv = inv_s;
    for (int i = tid; i < D_MODEL; i += 256) {
        x[i] = (x[i] - mu) * inv * w[i] + b[i];
    }
}

// ---------------------------------------------------------------------------
// Flash attention v3 (fp32, causal, ALiBi) — conflict-free float4 smem loads.
// Thread (tx,ty) in 16x16: S-tile rows ty*4+i, S-cols {tx + 16*j} (INTERLEAVED
// so quarter-warp B-loads at stride 132 cover all 32 banks). O cols tx*8..+7.
// grid = (S/64, H, B), 256 threads.
// ---------------------------------------------------------------------------
#define QSTR 132   /* Q tile row stride: 2 warp-row addrs land in diff banks */
#define KSTR 132   /* K tile row stride: tx+16j rows -> conflict-free LDS.128 */
#define PSTR 68    /* P tile row stride */

__global__ __launch_bounds__(256)
void attn_kernel(const float* __restrict__ qkv, float* __restrict__ outp) {
    extern __shared__ float smf[];
    float* Qs   = smf;                 // 64*132
    float* Ks   = Qs + 64*QSTR;        // 64*132
    float* Vs   = Ks + 64*KSTR;        // 64*128
    float* Ps   = Vs + 64*128;         // 64*68
    float* rowm = Ps + 64*PSTR;        // 64
    float* rowl = rowm + 64;           // 64
    float* rowr = rowl + 64;           // 64

    const int qt = blockIdx.x, h = blockIdx.y, b = blockIdx.z;
    const int tid = threadIdx.x;
    const int tx = tid & 15, ty = tid >> 4;
    const float scale = 0.08838834764831845f;            // 1/sqrt(128)
    const float slope = exp2f(-0.25f * (float)(h + 1));  // ALiBi, H == next_p2
    const size_t rowbase = (size_t)b * SEQ;

    // Load + pre-scale Q tile (float4), stride QSTR
    for (int i = tid; i < 64 * HDIM / 4; i += 256) {
        int r = i >> 5; int c = (i & 31) << 2;
        float4 v = *(const float4*)(qkv + (rowbase + qt*64 + r) * E3 + h*HDIM + c);
        v.x *= scale; v.y *= scale; v.z *= scale; v.w *= scale;
        *(float4*)(Qs + r*QSTR + c) = v;
    }
    if (tid < 64) { rowm[tid] = -1e30f; rowl[tid] = 0.f; }
    float o[4][8];
#pragma unroll
    for (int i = 0; i < 4; i++)
#pragma unroll
        for (int c = 0; c < 8; c++) o[i][c] = 0.f;
    __syncthreads();

    for (int kt = 0; kt <= qt; kt++) {
        // Load K (stride 132) and V tiles, float4 stores
        for (int i = tid; i < 64 * HDIM / 4; i += 256) {
            int r = i >> 5; int c = (i & 31) << 2;
            const float* kp = qkv + (rowbase + kt*64 + r) * E3 + D_MODEL + h*HDIM + c;
            *(float4*)(Ks + r*KSTR + c) = *(const float4*)kp;
            *(float4*)(Vs + r*HDIM + c) = *(const float4*)(kp + D_MODEL);
        }
        __syncthreads();

        // S = (Q*scale) K^T  — float4 smem loads, conflict-free
        float sacc[4][4] = {};
#pragma unroll 4
        for (int kb = 0; kb < HDIM; kb += 4) {
            float4 a4[4], b4[4];
#pragma unroll
            for (int i = 0; i < 4; i++)
                a4[i] = *(const float4*)(Qs + (ty*4+i)*QSTR + kb);
#pragma unroll
            for (int j = 0; j < 4; j++)
                b4[j] = *(const float4*)(Ks + (tx + 16*j)*KSTR + kb);
#pragma unroll
            for (int i = 0; i < 4; i++)
#pragma unroll
                for (int j = 0; j < 4; j++) {
                    sacc[i][j] = fmaf(a4[i].x, b4[j].x, sacc[i][j]);
                    sacc[i][j] = fmaf(a4[i].y, b4[j].y, sacc[i][j]);
                    sacc[i][j] = fmaf(a4[i].z, b4[j].z, sacc[i][j]);
                    sacc[i][j] = fmaf(a4[i].w, b4[j].w, sacc[i][j]);
                }
        }

        // ALiBi + causal mask -> Ps (scalar stores, cols tx+16j: conflict-free)
        const int qb = qt*64 + ty*4, kb0 = kt*64;
#pragma unroll
        for (int i = 0; i < 4; i++) {
            int qi = qb + i;
            float* prow = Ps + (ty*4+i)*PSTR;
#pragma unroll
            for (int j = 0; j < 4; j++) {
                int col = tx + 16*j;
                int kj = kb0 + col;
                float s = sacc[i][j] + slope * (float)(kj - qi);
                prow[col] = (kj > qi) ? -1e30f : s;
            }
        }
        __syncthreads();

        // Online softmax — 256 threads, 4 lanes/row, 16 cols each
        {
            const int row = tid >> 2;
            const int q4  = tid & 3;
            float4* p4 = (float4*)(Ps + row*PSTR + q4*16);
            float m_old = rowm[row];
            float4 x0 = p4[0], x1 = p4[1], x2 = p4[2], x3 = p4[3];
            float mx = fmaxf(fmaxf(fmaxf(x0.x, x0.y), fmaxf(x0.z, x0.w)),
                             fmaxf(fmaxf(x1.x, x1.y), fmaxf(x1.z, x1.w)));
            mx = fmaxf(mx, fmaxf(fmaxf(fmaxf(x2.x, x2.y), fmaxf(x2.z, x2.w)),
                                 fmaxf(fmaxf(x3.x, x3.y), fmaxf(x3.z, x3.w))));
            mx = fmaxf(mx, __shfl_xor_sync(0xffffffffu, mx, 1));
            mx = fmaxf(mx, __shfl_xor_sync(0xffffffffu, mx, 2));
            mx = fmaxf(mx, m_old);
            x0.x = __expf(x0.x - mx); x0.y = __expf(x0.y - mx);
            x0.z = __expf(x0.z - mx); x0.w = __expf(x0.w - mx);
            x1.x = __expf(x1.x - mx); x1.y = __expf(x1.y - mx);
            x1.z = __expf(x1.z - mx); x1.w = __expf(x1.w - mx);
            x2.x = __expf(x2.x - mx); x2.y = __expf(x2.y - mx);
            x2.z = __expf(x2.z - mx); x2.w = __expf(x2.w - mx);
            x3.x = __expf(x3.x - mx); x3.y = __expf(x3.y - mx);
            x3.z = __expf(x3.z - mx); x3.w = __expf(x3.w - mx);
            float sum = (x0.x + x0.y + x0.z + x0.w) + (x1.x + x1.y + x1.z + x1.w)
                      + (x2.x + x2.y + x2.z + x2.w) + (x3.x + x3.y + x3.z + x3.w);
            p4[0] = x0; p4[1] = x1; p4[2] = x2; p4[3] = x3;
            sum += __shfl_xor_sync(0xffffffffu, sum, 1);
            sum += __shfl_xor_sync(0xffffffffu, sum, 2);
            if (q4 == 0) {
                float r_ = __expf(m_old - mx);
                rowm[row] = mx;
                rowl[row] = rowl[row] * r_ + sum;
                rowr[row] = r_;
            }
        }
        __syncthreads();

        // Rescale O, accumulate P@V — float4 P loads (broadcast), V conflict-free
        float rr[4];
#pragma unroll
        for (int i = 0; i < 4; i++) rr[i] = rowr[ty*4+i];
#pragma unroll
        for (int i = 0; i < 4; i++)
#pragma unroll
            for (int c = 0; c < 8; c++) o[i][c] *= rr[i];
#pragma unroll 2
        for (int kb2 = 0; kb2 < 64; kb2 += 4) {
            float pv[4][4];
#pragma unroll
            for (int i = 0; i < 4; i++) {
                float4 p = *(const float4*)(Ps + (ty*4+i)*PSTR + kb2);
                pv[i][0] = p.x; pv[i][1] = p.y; pv[i][2] = p.z; pv[i][3] = p.w;
            }
#pragma unroll
            for (int t = 0; t < 4; t++) {
                float4 v0 = *(const float4*)(Vs + (kb2+t)*HDIM + tx*8);
                float4 v1 = *(const float4*)(Vs + (kb2+t)*HDIM + tx*8 + 4);
#pragma unroll
                for (int i = 0; i < 4; i++) {
                    float p = pv[i][t];
                    o[i][0] = fmaf(p, v0.x, o[i][0]);
                    o[i][1] = fmaf(p, v0.y, o[i][1]);
                    o[i][2] = fmaf(p, v0.z, o[i][2]);
                    o[i][3] = fmaf(p, v0.w, o[i][3]);
                    o[i][4] = fmaf(p, v1.x, o[i][4]);
                    o[i][5] = fmaf(p, v1.y, o[i][5]);
                    o[i][6] = fmaf(p, v1.z, o[i][6]);
                    o[i][7] = fmaf(p, v1.w, o[i][7]);
                }
            }
        }
        __syncthreads();
    }

    // Normalize and write
#pragma unroll
    for (int i = 0; i < 4; i++) {
        float inv = 1.f / rowl[ty*4+i];
        float* op = outp + (rowbase + qt*64 + ty*4 + i) * (size_t)D_MODEL + h*HDIM + tx*8;
        float4 w0 = make_float4(o[i][0]*inv, o[i][1]*inv, o[i][2]*inv, o[i][3]*inv);
        float4 w1 = make_float4(o[i][4]*inv, o[i][5]*inv, o[i][6]*inv, o[i][7]*inv);
        *(float4*)op = w0;
        *(float4*)(op + 4) = w1;
    }
}

#define ATTN_SMEM ((64*QSTR + 64*KSTR + 64*128 + 64*PSTR + 3*64) * (int)sizeof(float))

// ---------------------------------------------------------------------------
extern "C" void kernel_launch(void* const* d_in, const int* in_sizes, int n_in,
                              void* d_out, int out_size) {
    const float* hidden = (const float*)d_in[0];
    const float* w_qkv  = (const float*)d_in[1];
    const float* q_ln_w = (const float*)d_in[2];
    const float* q_ln_b = (const float*)d_in[3];
    const float* k_ln_w = (const float*)d_in[4];
    const float* k_ln_b = (const float*)d_in[5];
    const float* w_out  = (const float*)d_in[6];
    float* out = (float*)d_out;

    float *qkv, *attn;
    cudaGetSymbolAddress((void**)&qkv, g_qkv);
    cudaGetSymbolAddress((void**)&attn, g_attn);

    cudaFuncSetAttribute(gemm_mma<true>,  cudaFuncAttributeMaxDynamicSharedMemorySize, GEMM_SMEM);
    cudaFuncSetAttribute(gemm_mma<false>, cudaFuncAttributeMaxDynamicSharedMemorySize, GEMM_SMEM);
    cudaFuncSetAttribute(attn_kernel, cudaFuncAttributeMaxDynamicSharedMemorySize, ATTN_SMEM);

    // 1) QKV projection + clip (tf32 tensor cores)
    dim3 g1(E3 / 128, ROWS / 128);
    gemm_mma<true><<<g1, 256, GEMM_SMEM>>>(hidden, w_qkv, qkv, E3, D_MODEL);

    // 2) q/k LayerNorms
    ln_kernel<<<ROWS, 256>>>(qkv, 0,       q_ln_w, q_ln_b);
    ln_kernel<<<ROWS, 256>>>(qkv, D_MODEL, k_ln_w, k_ln_b);

    // 3) Flash attention (conflict-free vectorized)
    dim3 ga(SEQ / 64, NHEADS, BATCH);
    attn_kernel<<<ga, 256, ATTN_SMEM>>>(qkv, attn);

    // 4) Output projection -> d_out (tf32 tensor cores)
    dim3 g2(D_MODEL / 128, ROWS / 128);
    gemm_mma<false><<<g2, 256, GEMM_SMEM>>>(attn, w_out, out, D_MODEL, D_MODEL);
}

// round 6
// speedup vs baseline: 1.3718x; 1.2052x over previous
#include <cuda_runtime.h>
#include <cstdint>

#define D_MODEL 4096
#define E3      12288
#define NHEADS  32
#define HDIM    128
#define BATCH   2
#define SEQ     2048
#define ROWS    (BATCH*SEQ)   /* 4096 */
#define CLIP_V  8.0f
#define LN_EPS  1e-5f

// Scratch (allocation-free rule: __device__ globals)
__device__ float g_qkv[(size_t)ROWS * E3];       // [4096][12288] post-GEMM1 (q|k|v)
__device__ float g_attn[(size_t)ROWS * D_MODEL]; // [4096][4096]  attention output

// ===========================================================================
// mma.sync tf32 helpers (sm_80+)
// ===========================================================================
__device__ __forceinline__ uint32_t f2tf(float f) {
    uint32_t r;
    asm("cvt.rna.tf32.f32 %0, %1;" : "=r"(r) : "f"(f));
    return r;
}

__device__ __forceinline__ void mma_tf32(float* d, const uint32_t* a, const uint32_t* b) {
    asm volatile(
        "mma.sync.aligned.m16n8k8.row.col.f32.tf32.tf32.f32 "
        "{%0,%1,%2,%3}, {%4,%5,%6,%7}, {%8,%9}, {%0,%1,%2,%3};"
        : "+f"(d[0]), "+f"(d[1]), "+f"(d[2]), "+f"(d[3])
        : "r"(a[0]), "r"(a[1]), "r"(a[2]), "r"(a[3]), "r"(b[0]), "r"(b[1]));
}

// ===========================================================================
// TF32 GEMM v2: C[m][n] = sum_k A[m][k]*W[n][k]
// CTA tile 128x256, BK=16, 8 warps (2m x 4n), warp tile 64x64.
// Fragment LDS:HMMA = 1:1 (was 1.5:1), 2x MAC per crossbar byte.
// grid = (Ntot/256, M/128), 256 threads.
// ===========================================================================
#define BK2   16
#define LDP2  20                  /* padded stage row stride (words) */
#define A_TW  (128*LDP2)          /* A tile words */
#define B_TW  (256*LDP2)          /* B tile words */
#define GEMM_SMEM ((A_TW + B_TW) * 2 * 4)   /* 61440 B */

template<bool DO_CLIP>
__global__ __launch_bounds__(256)
void gemm_mma(const float* __restrict__ A, const float* __restrict__ W,
              float* __restrict__ C, int Ntot, int K) {
    extern __shared__ uint32_t sm[];
    uint32_t* As[2] = { sm,        sm + A_TW + B_TW };
    uint32_t* Bs[2] = { sm + A_TW, sm + 2*A_TW + B_TW };

    const int tid  = threadIdx.x;
    const int lane = tid & 31;
    const int warp = tid >> 5;
    const int wm0  = (warp >> 2) << 6;   // 0 or 64
    const int wn0  = (warp & 3) << 6;    // 0,64,128,192
    const int m0 = blockIdx.y << 7, n0 = blockIdx.x << 8;

    const float* Ab = A + (size_t)m0 * K;
    const float* Wb = W + (size_t)n0 * K;

    // LDG/STS mapping: slot = tid + 256*i; row = slot>>2 (= arow + 64*i), c4 = tid&3
    const int arow = tid >> 2;
    const int ac4  = tid & 3;

    float acc[4][8][4];
#pragma unroll
    for (int a = 0; a < 4; a++)
#pragma unroll
        for (int b = 0; b < 8; b++)
#pragma unroll
            for (int c = 0; c < 4; c++) acc[a][b][c] = 0.f;

    const int NS = K >> 4;               // BK=16 stages
    float4 pa[2], pb[4];

    // prefetch + store stage 0
#pragma unroll
    for (int i = 0; i < 2; i++)
        pa[i] = *(const float4*)(Ab + (size_t)(arow + 64*i) * K + ac4*4);
#pragma unroll
    for (int i = 0; i < 4; i++)
        pb[i] = *(const float4*)(Wb + (size_t)(arow + 64*i) * K + ac4*4);
#pragma unroll
    for (int i = 0; i < 2; i++) {
        uint32_t* p = As[0] + (arow + 64*i) * LDP2 + ac4*4;
        p[0] = f2tf(pa[i].x); p[1] = f2tf(pa[i].y);
        p[2] = f2tf(pa[i].z); p[3] = f2tf(pa[i].w);
    }
#pragma unroll
    for (int i = 0; i < 4; i++) {
        uint32_t* p = Bs[0] + (arow + 64*i) * LDP2 + ac4*4;
        p[0] = f2tf(pb[i].x); p[1] = f2tf(pb[i].y);
        p[2] = f2tf(pb[i].z); p[3] = f2tf(pb[i].w);
    }
    __syncthreads();

    for (int s = 0; s < NS; s++) {
        // prefetch next stage (global)
        if (s + 1 < NS) {
            const int k0 = (s + 1) << 4;
#pragma unroll
            for (int i = 0; i < 2; i++)
                pa[i] = *(const float4*)(Ab + (size_t)(arow + 64*i) * K + k0 + ac4*4);
#pragma unroll
            for (int i = 0; i < 4; i++)
                pb[i] = *(const float4*)(Wb + (size_t)(arow + 64*i) * K + k0 + ac4*4);
        }

        // compute current stage: 2 kk of m16n8k8 over 64x64 warp tile
        const uint32_t* Ac = As[s & 1];
        const uint32_t* Bc = Bs[s & 1];
#pragma unroll
        for (int kk = 0; kk < 2; kk++) {
            const int kb = kk << 3;
            const int c  = kb + (lane & 3);
            uint32_t af[4][4], bf[8][2];
#pragma unroll
            for (int mt = 0; mt < 4; mt++) {
                int r = wm0 + (mt << 4) + (lane >> 2);
                af[mt][0] = Ac[r * LDP2 + c];
                af[mt][1] = Ac[(r + 8) * LDP2 + c];
                af[mt][2] = Ac[r * LDP2 + c + 4];
                af[mt][3] = Ac[(r + 8) * LDP2 + c + 4];
            }
#pragma unroll
            for (int nt = 0; nt < 8; nt++) {
                int n = wn0 + (nt << 3) + (lane >> 2);
                bf[nt][0] = Bc[n * LDP2 + c];
                bf[nt][1] = Bc[n * LDP2 + c + 4];
            }
#pragma unroll
            for (int mt = 0; mt < 4; mt++)
#pragma unroll
                for (int nt = 0; nt < 8; nt++)
                    mma_tf32(acc[mt][nt], af[mt], bf[nt]);
        }

        // store next stage into the other buffer
        if (s + 1 < NS) {
            uint32_t* Ad = As[(s + 1) & 1];
            uint32_t* Bd = Bs[(s + 1) & 1];
#pragma unroll
            for (int i = 0; i < 2; i++) {
                uint32_t* p = Ad + (arow + 64*i) * LDP2 + ac4*4;
                p[0] = f2tf(pa[i].x); p[1] = f2tf(pa[i].y);
                p[2] = f2tf(pa[i].z); p[3] = f2tf(pa[i].w);
            }
#pragma unroll
            for (int i = 0; i < 4; i++) {
                uint32_t* p = Bd + (arow + 64*i) * LDP2 + ac4*4;
                p[0] = f2tf(pb[i].x); p[1] = f2tf(pb[i].y);
                p[2] = f2tf(pb[i].z); p[3] = f2tf(pb[i].w);
            }
            __syncthreads();
        }
    }

    // epilogue
#pragma unroll
    for (int mt = 0; mt < 4; mt++) {
#pragma unroll
        for (int nt = 0; nt < 8; nt++) {
            int row = m0 + wm0 + (mt << 4) + (lane >> 2);
            int col = n0 + wn0 + (nt << 3) + ((lane & 3) << 1);
            float2 v0 = make_float2(acc[mt][nt][0], acc[mt][nt][1]);
            float2 v1 = make_float2(acc[mt][nt][2], acc[mt][nt][3]);
            if (DO_CLIP) {
                v0.x = fminf(fmaxf(v0.x, -CLIP_V), CLIP_V);
                v0.y = fminf(fmaxf(v0.y, -CLIP_V), CLIP_V);
                v1.x = fminf(fmaxf(v1.x, -CLIP_V), CLIP_V);
                v1.y = fminf(fmaxf(v1.y, -CLIP_V), CLIP_V);
            }
            *(float2*)(C + (size_t)row * Ntot + col) = v0;
            *(float2*)(C + (size_t)(row + 8) * Ntot + col) = v1;
        }
    }
}

// ---------------------------------------------------------------------------
// LayerNorm (unchanged)
// ---------------------------------------------------------------------------
__global__ __launch_bounds__(256)
void ln_kernel(float* __restrict__ base, int col_off,
               const float* __restrict__ w, const float* __restrict__ b) {
    __shared__ float red0[8], red1[8];
    __shared__ float mu_s, inv_s;
    float* x = base + (size_t)blockIdx.x * E3 + col_off;
    const int tid = threadIdx.x;

    float s = 0.f, s2 = 0.f;
    for (int i = tid; i < D_MODEL; i += 256) {
        float v = x[i]; s += v; s2 += v * v;
    }
#pragma unroll
    for (int o = 16; o; o >>= 1) {
        s  += __shfl_down_sync(0xffffffffu, s,  o);
        s2 += __shfl_down_sync(0xffffffffu, s2, o);
    }
    if ((tid & 31) == 0) { red0[tid >> 5] = s; red1[tid >> 5] = s2; }
    __syncthreads();
    if (tid == 0) {
        float S = 0.f, S2 = 0.f;
#pragma unroll
        for (int i = 0; i < 8; i++) { S += red0[i]; S2 += red1[i]; }
        float mu = S * (1.f / D_MODEL);
        float var = S2 * (1.f / D_MODEL) - mu * mu;
        mu_s = mu;
        inv_s = rsqrtf(var + LN_EPS);
    }
    __syncthreads();
    const float mu = mu_s, inv = inv_s;
    for (int i = tid; i < D_MODEL; i += 256) {
        x[i] = (x[i] - mu) * inv * w[i] + b[i];
    }
}

// ---------------------------------------------------------------------------
// Flash attention v3 (unchanged from R5 — conflict-free float4 smem loads)
// ---------------------------------------------------------------------------
#define QSTR 132
#define KSTR 132
#define PSTR 68

__global__ __launch_bounds__(256)
void attn_kernel(const float* __restrict__ qkv, float* __restrict__ outp) {
    extern __shared__ float smf[];
    float* Qs   = smf;                 // 64*132
    float* Ks   = Qs + 64*QSTR;        // 64*132
    float* Vs   = Ks + 64*KSTR;        // 64*128
    float* Ps   = Vs + 64*128;         // 64*68
    float* rowm = Ps + 64*PSTR;        // 64
    float* rowl = rowm + 64;           // 64
    float* rowr = rowl + 64;           // 64

    const int qt = blockIdx.x, h = blockIdx.y, b = blockIdx.z;
    const int tid = threadIdx.x;
    const int tx = tid & 15, ty = tid >> 4;
    const float scale = 0.08838834764831845f;            // 1/sqrt(128)
    const float slope = exp2f(-0.25f * (float)(h + 1));  // ALiBi, H == next_p2
    const size_t rowbase = (size_t)b * SEQ;

    for (int i = tid; i < 64 * HDIM / 4; i += 256) {
        int r = i >> 5; int c = (i & 31) << 2;
        float4 v = *(const float4*)(qkv + (rowbase + qt*64 + r) * E3 + h*HDIM + c);
        v.x *= scale; v.y *= scale; v.z *= scale; v.w *= scale;
        *(float4*)(Qs + r*QSTR + c) = v;
    }
    if (tid < 64) { rowm[tid] = -1e30f; rowl[tid] = 0.f; }
    float o[4][8];
#pragma unroll
    for (int i = 0; i < 4; i++)
#pragma unroll
        for (int c = 0; c < 8; c++) o[i][c] = 0.f;
    __syncthreads();

    for (int kt = 0; kt <= qt; kt++) {
        for (int i = tid; i < 64 * HDIM / 4; i += 256) {
            int r = i >> 5; int c = (i & 31) << 2;
            const float* kp = qkv + (rowbase + kt*64 + r) * E3 + D_MODEL + h*HDIM + c;
            *(float4*)(Ks + r*KSTR + c) = *(const float4*)kp;
            *(float4*)(Vs + r*HDIM + c) = *(const float4*)(kp + D_MODEL);
        }
        __syncthreads();

        float sacc[4][4] = {};
#pragma unroll 4
        for (int kb = 0; kb < HDIM; kb += 4) {
            float4 a4[4], b4[4];
#pragma unroll
            for (int i = 0; i < 4; i++)
                a4[i] = *(const float4*)(Qs + (ty*4+i)*QSTR + kb);
#pragma unroll
            for (int j = 0; j < 4; j++)
                b4[j] = *(const float4*)(Ks + (tx + 16*j)*KSTR + kb);
#pragma unroll
            for (int i = 0; i < 4; i++)
#pragma unroll
                for (int j = 0; j < 4; j++) {
                    sacc[i][j] = fmaf(a4[i].x, b4[j].x, sacc[i][j]);
                    sacc[i][j] = fmaf(a4[i].y, b4[j].y, sacc[i][j]);
                    sacc[i][j] = fmaf(a4[i].z, b4[j].z, sacc[i][j]);
                    sacc[i][j] = fmaf(a4[i].w, b4[j].w, sacc[i][j]);
                }
        }

        const int qb = qt*64 + ty*4, kb0 = kt*64;
#pragma unroll
        for (int i = 0; i < 4; i++) {
            int qi = qb + i;
            float* prow = Ps + (ty*4+i)*PSTR;
#pragma unroll
            for (int j = 0; j < 4; j++) {
                int col = tx + 16*j;
                int kj = kb0 + col;
                float s = sacc[i][j] + slope * (float)(kj - qi);
                prow[col] = (kj > qi) ? -1e30f : s;
            }
        }
        __syncthreads();

        {
            const int row = tid >> 2;
            const int q4  = tid & 3;
            float4* p4 = (float4*)(Ps + row*PSTR + q4*16);
            float m_old = rowm[row];
            float4 x0 = p4[0], x1 = p4[1], x2 = p4[2], x3 = p4[3];
            float mx = fmaxf(fmaxf(fmaxf(x0.x, x0.y), fmaxf(x0.z, x0.w)),
                             fmaxf(fmaxf(x1.x, x1.y), fmaxf(x1.z, x1.w)));
            mx = fmaxf(mx, fmaxf(fmaxf(fmaxf(x2.x, x2.y), fmaxf(x2.z, x2.w)),
                                 fmaxf(fmaxf(x3.x, x3.y), fmaxf(x3.z, x3.w))));
            mx = fmaxf(mx, __shfl_xor_sync(0xffffffffu, mx, 1));
            mx = fmaxf(mx, __shfl_xor_sync(0xffffffffu, mx, 2));
            mx = fmaxf(mx, m_old);
            x0.x = __expf(x0.x - mx); x0.y = __expf(x0.y - mx);
            x0.z = __expf(x0.z - mx); x0.w = __expf(x0.w - mx);
            x1.x = __expf(x1.x - mx); x1.y = __expf(x1.y - mx);
            x1.z = __expf(x1.z - mx); x1.w = __expf(x1.w - mx);
            x2.x = __expf(x2.x - mx); x2.y = __expf(x2.y - mx);
            x2.z = __expf(x2.z - mx); x2.w = __expf(x2.w - mx);
            x3.x = __expf(x3.x - mx); x3.y = __expf(x3.y - mx);
            x3.z = __expf(x3.z - mx); x3.w = __expf(x3.w - mx);
            float sum = (x0.x + x0.y + x0.z + x0.w) + (x1.x + x1.y + x1.z + x1.w)
                      + (x2.x + x2.y + x2.z + x2.w) + (x3.x + x3.y + x3.z + x3.w);
            p4[0] = x0; p4[1] = x1; p4[2] = x2; p4[3] = x3;
            sum += __shfl_xor_sync(0xffffffffu, sum, 1);
            sum += __shfl_xor_sync(0xffffffffu, sum, 2);
            if (q4 == 0) {
                float r_ = __expf(m_old - mx);
                rowm[row] = mx;
                rowl[row] = rowl[row] * r_ + sum;
                rowr[row] = r_;
            }
        }
        __syncthreads();

        float rr[4];
#pragma unroll
        for (int i = 0; i < 4; i++) rr[i] = rowr[ty*4+i];
#pragma unroll
        for (int i = 0; i < 4; i++)
#pragma unroll
            for (int c = 0; c < 8; c++) o[i][c] *= rr[i];
#pragma unroll 2
        for (int kb2 = 0; kb2 < 64; kb2 += 4) {
            float pv[4][4];
#pragma unroll
            for (int i = 0; i < 4; i++) {
                float4 p = *(const float4*)(Ps + (ty*4+i)*PSTR + kb2);
                pv[i][0] = p.x; pv[i][1] = p.y; pv[i][2] = p.z; pv[i][3] = p.w;
            }
#pragma unroll
            for (int t = 0; t < 4; t++) {
                float4 v0 = *(const float4*)(Vs + (kb2+t)*HDIM + tx*8);
                float4 v1 = *(const float4*)(Vs + (kb2+t)*HDIM + tx*8 + 4);
#pragma unroll
                for (int i = 0; i < 4; i++) {
                    float p = pv[i][t];
                    o[i][0] = fmaf(p, v0.x, o[i][0]);
                    o[i][1] = fmaf(p, v0.y, o[i][1]);
                    o[i][2] = fmaf(p, v0.z, o[i][2]);
                    o[i][3] = fmaf(p, v0.w, o[i][3]);
                    o[i][4] = fmaf(p, v1.x, o[i][4]);
                    o[i][5] = fmaf(p, v1.y, o[i][5]);
                    o[i][6] = fmaf(p, v1.z, o[i][6]);
                    o[i][7] = fmaf(p, v1.w, o[i][7]);
                }
            }
        }
        __syncthreads();
    }

#pragma unroll
    for (int i = 0; i < 4; i++) {
        float inv = 1.f / rowl[ty*4+i];
        float* op = outp + (rowbase + qt*64 + ty*4 + i) * (size_t)D_MODEL + h*HDIM + tx*8;
        float4 w0 = make_float4(o[i][0]*inv, o[i][1]*inv, o[i][2]*inv, o[i][3]*inv);
        float4 w1 = make_float4(o[i][4]*inv, o[i][5]*inv, o[i][6]*inv, o[i][7]*inv);
        *(float4*)op = w0;
        *(float4*)(op + 4) = w1;
    }
}

#define ATTN_SMEM ((64*QSTR + 64*KSTR + 64*128 + 64*PSTR + 3*64) * (int)sizeof(float))

// ---------------------------------------------------------------------------
extern "C" void kernel_launch(void* const* d_in, const int* in_sizes, int n_in,
                              void* d_out, int out_size) {
    const float* hidden = (const float*)d_in[0];
    const float* w_qkv  = (const float*)d_in[1];
    const float* q_ln_w = (const float*)d_in[2];
    const float* q_ln_b = (const float*)d_in[3];
    const float* k_ln_w = (const float*)d_in[4];
    const float* k_ln_b = (const float*)d_in[5];
    const float* w_out  = (const float*)d_in[6];
    float* out = (float*)d_out;

    float *qkv, *attn;
    cudaGetSymbolAddress((void**)&qkv, g_qkv);
    cudaGetSymbolAddress((void**)&attn, g_attn);

    cudaFuncSetAttribute(gemm_mma<true>,  cudaFuncAttributeMaxDynamicSharedMemorySize, GEMM_SMEM);
    cudaFuncSetAttribute(gemm_mma<false>, cudaFuncAttributeMaxDynamicSharedMemorySize, GEMM_SMEM);
    cudaFuncSetAttribute(attn_kernel, cudaFuncAttributeMaxDynamicSharedMemorySize, ATTN_SMEM);

    // 1) QKV projection + clip (tf32, 128x256 tiles)
    dim3 g1(E3 / 256, ROWS / 128);
    gemm_mma<true><<<g1, 256, GEMM_SMEM>>>(hidden, w_qkv, qkv, E3, D_MODEL);

    // 2) q/k LayerNorms
    ln_kernel<<<ROWS, 256>>>(qkv, 0,       q_ln_w, q_ln_b);
    ln_kernel<<<ROWS, 256>>>(qkv, D_MODEL, k_ln_w, k_ln_b);

    // 3) Flash attention
    dim3 ga(SEQ / 64, NHEADS, BATCH);
    attn_kernel<<<ga, 256, ATTN_SMEM>>>(qkv, attn);

    // 4) Output projection -> d_out (tf32, 128x256 tiles)
    dim3 g2(D_MODEL / 256, ROWS / 128);
    gemm_mma<false><<<g2, 256, GEMM_SMEM>>>(attn, w_out, out, D_MODEL, D_MODEL);
}

// round 7
// speedup vs baseline: 1.4889x; 1.0854x over previous
#include <cuda_runtime.h>
#include <cstdint>

#define D_MODEL 4096
#define E3      12288
#define NHEADS  32
#define HDIM    128
#define BATCH   2
#define SEQ     2048
#define ROWS    (BATCH*SEQ)   /* 4096 */
#define CLIP_V  8.0f
#define LN_EPS  1e-5f

// Scratch (allocation-free rule: __device__ globals)
__device__ float g_qkv[(size_t)ROWS * E3];       // [4096][12288] post-GEMM1 (q|k|v)
__device__ float g_attn[(size_t)ROWS * D_MODEL]; // [4096][4096]  attention output

// ===========================================================================
// mma.sync tf32 helpers (sm_80+)
// ===========================================================================
__device__ __forceinline__ uint32_t f2tf(float f) {
    uint32_t r;
    asm("cvt.rna.tf32.f32 %0, %1;" : "=r"(r) : "f"(f));
    return r;
}

__device__ __forceinline__ void mma_tf32(float* d, const uint32_t* a, const uint32_t* b) {
    asm volatile(
        "mma.sync.aligned.m16n8k8.row.col.f32.tf32.tf32.f32 "
        "{%0,%1,%2,%3}, {%4,%5,%6,%7}, {%8,%9}, {%0,%1,%2,%3};"
        : "+f"(d[0]), "+f"(d[1]), "+f"(d[2]), "+f"(d[3])
        : "r"(a[0]), "r"(a[1]), "r"(a[2]), "r"(a[3]), "r"(b[0]), "r"(b[1]));
}

// ===========================================================================
// TF32 GEMM v3: C[m][n] = sum_k A[m][k]*W[n][k]
// CTA tile 128x256, BK=32 (half the barriers of BK=16), 8 warps (2m x 4n),
// warp tile 64x64. grid = (Ntot/256, M/128), 256 threads.
// ===========================================================================
#define LDP2  36                  /* padded stage row stride (words) */
#define A_TW  (128*LDP2)          /* A tile words: 4608 */
#define B_TW  (256*LDP2)          /* B tile words: 9216 */
#define GEMM_SMEM ((A_TW + B_TW) * 2 * 4)   /* 110592 B */

template<bool DO_CLIP>
__global__ __launch_bounds__(256)
void gemm_mma(const float* __restrict__ A, const float* __restrict__ W,
              float* __restrict__ C, int Ntot, int K) {
    extern __shared__ uint32_t sm[];
    uint32_t* As[2] = { sm,        sm + A_TW + B_TW };
    uint32_t* Bs[2] = { sm + A_TW, sm + 2*A_TW + B_TW };

    const int tid  = threadIdx.x;
    const int lane = tid & 31;
    const int warp = tid >> 5;
    const int wm0  = (warp >> 2) << 6;   // 0 or 64
    const int wn0  = (warp & 3) << 6;    // 0,64,128,192
    const int m0 = blockIdx.y << 7, n0 = blockIdx.x << 8;

    const float* Ab = A + (size_t)m0 * K;
    const float* Wb = W + (size_t)n0 * K;

    // LDG/STS mapping: slot = tid + 256*i; row = slot>>3, c4 = tid&7
    const int arow = tid >> 3;
    const int ac4  = tid & 7;

    float acc[4][8][4];
#pragma unroll
    for (int a = 0; a < 4; a++)
#pragma unroll
        for (int b = 0; b < 8; b++)
#pragma unroll
            for (int c = 0; c < 4; c++) acc[a][b][c] = 0.f;

    const int NS = K >> 5;               // BK=32 stages
    float4 pa[4], pb[8];

    // prefetch + store stage 0
#pragma unroll
    for (int i = 0; i < 4; i++)
        pa[i] = *(const float4*)(Ab + (size_t)(arow + 32*i) * K + ac4*4);
#pragma unroll
    for (int i = 0; i < 8; i++)
        pb[i] = *(const float4*)(Wb + (size_t)(arow + 32*i) * K + ac4*4);
#pragma unroll
    for (int i = 0; i < 4; i++) {
        uint32_t* p = As[0] + (arow + 32*i) * LDP2 + ac4*4;
        p[0] = f2tf(pa[i].x); p[1] = f2tf(pa[i].y);
        p[2] = f2tf(pa[i].z); p[3] = f2tf(pa[i].w);
    }
#pragma unroll
    for (int i = 0; i < 8; i++) {
        uint32_t* p = Bs[0] + (arow + 32*i) * LDP2 + ac4*4;
        p[0] = f2tf(pb[i].x); p[1] = f2tf(pb[i].y);
        p[2] = f2tf(pb[i].z); p[3] = f2tf(pb[i].w);
    }
    __syncthreads();

    for (int s = 0; s < NS; s++) {
        // prefetch next stage (global)
        if (s + 1 < NS) {
            const int k0 = (s + 1) << 5;
#pragma unroll
            for (int i = 0; i < 4; i++)
                pa[i] = *(const float4*)(Ab + (size_t)(arow + 32*i) * K + k0 + ac4*4);
#pragma unroll
            for (int i = 0; i < 8; i++)
                pb[i] = *(const float4*)(Wb + (size_t)(arow + 32*i) * K + k0 + ac4*4);
        }

        // compute current stage: 4 kk of m16n8k8 over 64x64 warp tile
        const uint32_t* Ac = As[s & 1];
        const uint32_t* Bc = Bs[s & 1];
#pragma unroll
        for (int kk = 0; kk < 4; kk++) {
            const int c = (kk << 3) + (lane & 3);
            uint32_t af[4][4], bf[8][2];
#pragma unroll
            for (int mt = 0; mt < 4; mt++) {
                int r = wm0 + (mt << 4) + (lane >> 2);
                af[mt][0] = Ac[r * LDP2 + c];
                af[mt][1] = Ac[(r + 8) * LDP2 + c];
                af[mt][2] = Ac[r * LDP2 + c + 4];
                af[mt][3] = Ac[(r + 8) * LDP2 + c + 4];
            }
#pragma unroll
            for (int nt = 0; nt < 8; nt++) {
                int n = wn0 + (nt << 3) + (lane >> 2);
                bf[nt][0] = Bc[n * LDP2 + c];
                bf[nt][1] = Bc[n * LDP2 + c + 4];
            }
#pragma unroll
            for (int mt = 0; mt < 4; mt++)
#pragma unroll
                for (int nt = 0; nt < 8; nt++)
                    mma_tf32(acc[mt][nt], af[mt], bf[nt]);
        }

        // store next stage into the other buffer
        if (s + 1 < NS) {
            uint32_t* Ad = As[(s + 1) & 1];
            uint32_t* Bd = Bs[(s + 1) & 1];
#pragma unroll
            for (int i = 0; i < 4; i++) {
                uint32_t* p = Ad + (arow + 32*i) * LDP2 + ac4*4;
                p[0] = f2tf(pa[i].x); p[1] = f2tf(pa[i].y);
                p[2] = f2tf(pa[i].z); p[3] = f2tf(pa[i].w);
            }
#pragma unroll
            for (int i = 0; i < 8; i++) {
                uint32_t* p = Bd + (arow + 32*i) * LDP2 + ac4*4;
                p[0] = f2tf(pb[i].x); p[1] = f2tf(pb[i].y);
                p[2] = f2tf(pb[i].z); p[3] = f2tf(pb[i].w);
            }
            __syncthreads();
        }
    }

    // epilogue
#pragma unroll
    for (int mt = 0; mt < 4; mt++) {
#pragma unroll
        for (int nt = 0; nt < 8; nt++) {
            int row = m0 + wm0 + (mt << 4) + (lane >> 2);
            int col = n0 + wn0 + (nt << 3) + ((lane & 3) << 1);
            float2 v0 = make_float2(acc[mt][nt][0], acc[mt][nt][1]);
            float2 v1 = make_float2(acc[mt][nt][2], acc[mt][nt][3]);
            if (DO_CLIP) {
                v0.x = fminf(fmaxf(v0.x, -CLIP_V), CLIP_V);
                v0.y = fminf(fmaxf(v0.y, -CLIP_V), CLIP_V);
                v1.x = fminf(fmaxf(v1.x, -CLIP_V), CLIP_V);
                v1.y = fminf(fmaxf(v1.y, -CLIP_V), CLIP_V);
            }
            *(float2*)(C + (size_t)row * Ntot + col) = v0;
            *(float2*)(C + (size_t)(row + 8) * Ntot + col) = v1;
        }
    }
}

// ---------------------------------------------------------------------------
// LayerNorm (unchanged)
// ---------------------------------------------------------------------------
__global__ __launch_bounds__(256)
void ln_kernel(float* __restrict__ base, int col_off,
               const float* __restrict__ w, const float* __restrict__ b) {
    __shared__ float red0[8], red1[8];
    __shared__ float mu_s, inv_s;
    float* x = base + (size_t)blockIdx.x * E3 + col_off;
    const int tid = threadIdx.x;

    float s = 0.f, s2 = 0.f;
    for (int i = tid; i < D_MODEL; i += 256) {
        float v = x[i]; s += v; s2 += v * v;
    }
#pragma unroll
    for (int o = 16; o; o >>= 1) {
        s  += __shfl_down_sync(0xffffffffu, s,  o);
        s2 += __shfl_down_sync(0xffffffffu, s2, o);
    }
    if ((tid & 31) == 0) { red0[tid >> 5] = s; red1[tid >> 5] = s2; }
    __syncthreads();
    if (tid == 0) {
        float S = 0.f, S2 = 0.f;
#pragma unroll
        for (int i = 0; i < 8; i++) { S += red0[i]; S2 += red1[i]; }
        float mu = S * (1.f / D_MODEL);
        float var = S2 * (1.f / D_MODEL) - mu * mu;
        mu_s = mu;
        inv_s = rsqrtf(var + LN_EPS);
    }
    __syncthreads();
    const float mu = mu_s, inv = inv_s;
    for (int i = tid; i < D_MODEL; i += 256) {
        x[i] = (x[i] - mu) * inv * w[i] + b[i];
    }
}

// ---------------------------------------------------------------------------
// Flash attention v4: register softmax via half-warp shuffles.
// The 16 lanes with equal ty (a half-warp) own S-rows ty*4+i and S-cols
// tx+16j — row reductions are 4x shfl_xor(1,2,4,8). No Ps re-read pass,
// no rowr array, 2 barriers/tile instead of 4.
// ---------------------------------------------------------------------------
#define QSTR 132
#define KSTR 132
#define PSTR 68

__global__ __launch_bounds__(256)
void attn_kernel(const float* __restrict__ qkv, float* __restrict__ outp) {
    extern __shared__ float smf[];
    float* Qs   = smf;                 // 64*132
    float* Ks   = Qs + 64*QSTR;        // 64*132
    float* Vs   = Ks + 64*KSTR;        // 64*128
    float* Ps   = Vs + 64*128;         // 64*68
    float* rowm = Ps + 64*PSTR;        // 64
    float* rowl = rowm + 64;           // 64

    const int qt = blockIdx.x, h = blockIdx.y, b = blockIdx.z;
    const int tid = threadIdx.x;
    const int tx = tid & 15, ty = tid >> 4;
    const float scale = 0.08838834764831845f;            // 1/sqrt(128)
    const float slope = exp2f(-0.25f * (float)(h + 1));  // ALiBi, H == next_p2
    const size_t rowbase = (size_t)b * SEQ;

    for (int i = tid; i < 64 * HDIM / 4; i += 256) {
        int r = i >> 5; int c = (i & 31) << 2;
        float4 v = *(const float4*)(qkv + (rowbase + qt*64 + r) * E3 + h*HDIM + c);
        v.x *= scale; v.y *= scale; v.z *= scale; v.w *= scale;
        *(float4*)(Qs + r*QSTR + c) = v;
    }
    if (tid < 64) { rowm[tid] = -1e30f; rowl[tid] = 0.f; }
    float o[4][8];
#pragma unroll
    for (int i = 0; i < 4; i++)
#pragma unroll
        for (int c = 0; c < 8; c++) o[i][c] = 0.f;
    __syncthreads();

    for (int kt = 0; kt <= qt; kt++) {
        // Load K (stride 132) and V tiles
        for (int i = tid; i < 64 * HDIM / 4; i += 256) {
            int r = i >> 5; int c = (i & 31) << 2;
            const float* kp = qkv + (rowbase + kt*64 + r) * E3 + D_MODEL + h*HDIM + c;
            *(float4*)(Ks + r*KSTR + c) = *(const float4*)kp;
            *(float4*)(Vs + r*HDIM + c) = *(const float4*)(kp + D_MODEL);
        }
        __syncthreads();

        // S = (Q*scale) K^T  — float4 smem loads, conflict-free
        float sacc[4][4] = {};
#pragma unroll 4
        for (int kb = 0; kb < HDIM; kb += 4) {
            float4 a4[4], b4[4];
#pragma unroll
            for (int i = 0; i < 4; i++)
                a4[i] = *(const float4*)(Qs + (ty*4+i)*QSTR + kb);
#pragma unroll
            for (int j = 0; j < 4; j++)
                b4[j] = *(const float4*)(Ks + (tx + 16*j)*KSTR + kb);
#pragma unroll
            for (int i = 0; i < 4; i++)
#pragma unroll
                for (int j = 0; j < 4; j++) {
                    sacc[i][j] = fmaf(a4[i].x, b4[j].x, sacc[i][j]);
                    sacc[i][j] = fmaf(a4[i].y, b4[j].y, sacc[i][j]);
                    sacc[i][j] = fmaf(a4[i].z, b4[j].z, sacc[i][j]);
                    sacc[i][j] = fmaf(a4[i].w, b4[j].w, sacc[i][j]);
                }
        }

        // Bias + mask + online softmax fully in registers (half-warp shfl)
        const int qb = qt*64 + ty*4, kb0 = kt*64;
        float r_[4];
#pragma unroll
        for (int i = 0; i < 4; i++) {
            const int row = ty*4 + i;
            const int qi  = qb + i;
            float v[4];
#pragma unroll
            for (int j = 0; j < 4; j++) {
                int kj = kb0 + tx + 16*j;
                float s = sacc[i][j] + slope * (float)(kj - qi);
                v[j] = (kj > qi) ? -1e30f : s;
            }
            float mx = fmaxf(fmaxf(v[0], v[1]), fmaxf(v[2], v[3]));
            mx = fmaxf(mx, __shfl_xor_sync(0xffffffffu, mx, 1));
            mx = fmaxf(mx, __shfl_xor_sync(0xffffffffu, mx, 2));
            mx = fmaxf(mx, __shfl_xor_sync(0xffffffffu, mx, 4));
            mx = fmaxf(mx, __shfl_xor_sync(0xffffffffu, mx, 8));
            float mo = rowm[row];
            float mn = fmaxf(mx, mo);
#pragma unroll
            for (int j = 0; j < 4; j++) v[j] = __expf(v[j] - mn);
            float sum = (v[0] + v[1]) + (v[2] + v[3]);
            sum += __shfl_xor_sync(0xffffffffu, sum, 1);
            sum += __shfl_xor_sync(0xffffffffu, sum, 2);
            sum += __shfl_xor_sync(0xffffffffu, sum, 4);
            sum += __shfl_xor_sync(0xffffffffu, sum, 8);
            r_[i] = __expf(mo - mn);
            if (tx == 0) {
                rowm[row] = mn;
                rowl[row] = rowl[row] * r_[i] + sum;
            }
            // write exp'd P (cols tx+16j -> banks cover all 32, conflict-free)
            float* prow = Ps + row*PSTR;
#pragma unroll
            for (int j = 0; j < 4; j++) prow[tx + 16*j] = v[j];
        }
        __syncwarp();   // P rows are produced & consumed by the same half-warp

        // Rescale O, accumulate P@V
#pragma unroll
        for (int i = 0; i < 4; i++)
#pragma unroll
            for (int c = 0; c < 8; c++) o[i][c] *= r_[i];
#pragma unroll 2
        for (int kb2 = 0; kb2 < 64; kb2 += 4) {
            float pv[4][4];
#pragma unroll
            for (int i = 0; i < 4; i++) {
                float4 p = *(const float4*)(Ps + (ty*4+i)*PSTR + kb2);
                pv[i][0] = p.x; pv[i][1] = p.y; pv[i][2] = p.z; pv[i][3] = p.w;
            }
#pragma unroll
            for (int t = 0; t < 4; t++) {
                float4 v0 = *(const float4*)(Vs + (kb2+t)*HDIM + tx*8);
                float4 v1 = *(const float4*)(Vs + (kb2+t)*HDIM + tx*8 + 4);
#pragma unroll
                for (int i = 0; i < 4; i++) {
                    float p = pv[i][t];
                    o[i][0] = fmaf(p, v0.x, o[i][0]);
                    o[i][1] = fmaf(p, v0.y, o[i][1]);
                    o[i][2] = fmaf(p, v0.z, o[i][2]);
                    o[i][3] = fmaf(p, v0.w, o[i][3]);
                    o[i][4] = fmaf(p, v1.x, o[i][4]);
                    o[i][5] = fmaf(p, v1.y, o[i][5]);
                    o[i][6] = fmaf(p, v1.z, o[i][6]);
                    o[i][7] = fmaf(p, v1.w, o[i][7]);
                }
            }
        }
        __syncthreads();   // protect Ks/Vs before next tile's load
    }

    // Normalize and write
#pragma unroll
    for (int i = 0; i < 4; i++) {
        float inv = 1.f / rowl[ty*4+i];
        float* op = outp + (rowbase + qt*64 + ty*4 + i) * (size_t)D_MODEL + h*HDIM + tx*8;
        float4 w0 = make_float4(o[i][0]*inv, o[i][1]*inv, o[i][2]*inv, o[i][3]*inv);
        float4 w1 = make_float4(o[i][4]*inv, o[i][5]*inv, o[i][6]*inv, o[i][7]*inv);
        *(float4*)op = w0;
        *(float4*)(op + 4) = w1;
    }
}

#define ATTN_SMEM ((64*QSTR + 64*KSTR + 64*128 + 64*PSTR + 2*64) * (int)sizeof(float))

// ---------------------------------------------------------------------------
extern "C" void kernel_launch(void* const* d_in, const int* in_sizes, int n_in,
                              void* d_out, int out_size) {
    const float* hidden = (const float*)d_in[0];
    const float* w_qkv  = (const float*)d_in[1];
    const float* q_ln_w = (const float*)d_in[2];
    const float* q_ln_b = (const float*)d_in[3];
    const float* k_ln_w = (const float*)d_in[4];
    const float* k_ln_b = (const float*)d_in[5];
    const float* w_out  = (const float*)d_in[6];
    float* out = (float*)d_out;

    float *qkv, *attn;
    cudaGetSymbolAddress((void**)&qkv, g_qkv);
    cudaGetSymbolAddress((void**)&attn, g_attn);

    cudaFuncSetAttribute(gemm_mma<true>,  cudaFuncAttributeMaxDynamicSharedMemorySize, GEMM_SMEM);
    cudaFuncSetAttribute(gemm_mma<false>, cudaFuncAttributeMaxDynamicSharedMemorySize, GEMM_SMEM);
    cudaFuncSetAttribute(attn_kernel, cudaFuncAttributeMaxDynamicSharedMemorySize, ATTN_SMEM);

    // 1) QKV projection + clip (tf32, 128x256 tiles, BK=32)
    dim3 g1(E3 / 256, ROWS / 128);
    gemm_mma<true><<<g1, 256, GEMM_SMEM>>>(hidden, w_qkv, qkv, E3, D_MODEL);

    // 2) q/k LayerNorms
    ln_kernel<<<ROWS, 256>>>(qkv, 0,       q_ln_w, q_ln_b);
    ln_kernel<<<ROWS, 256>>>(qkv, D_MODEL, k_ln_w, k_ln_b);

    // 3) Flash attention (register softmax)
    dim3 ga(SEQ / 64, NHEADS, BATCH);
    attn_kernel<<<ga, 256, ATTN_SMEM>>>(qkv, attn);

    // 4) Output projection -> d_out (tf32, 128x256 tiles, BK=32)
    dim3 g2(D_MODEL / 256, ROWS / 128);
    gemm_mma<false><<<g2, 256, GEMM_SMEM>>>(attn, w_out, out, D_MODEL, D_MODEL);
}

// round 8
// speedup vs baseline: 1.5452x; 1.0377x over previous
#include <cuda_runtime.h>
#include <cstdint>

#define D_MODEL 4096
#define E3      12288
#define NHEADS  32
#define HDIM    128
#define BATCH   2
#define SEQ     2048
#define ROWS    (BATCH*SEQ)   /* 4096 */
#define CLIP_V  8.0f
#define LN_EPS  1e-5f

// Scratch (allocation-free rule: __device__ globals)
__device__ float g_qkv[(size_t)ROWS * E3];       // [4096][12288] post-GEMM1 (q|k|v)
__device__ float g_attn[(size_t)ROWS * D_MODEL]; // [4096][4096]  attention output

// ===========================================================================
// mma.sync tf32 helpers (sm_80+)
// ===========================================================================
__device__ __forceinline__ uint32_t f2tf(float f) {
    uint32_t r;
    asm("cvt.rna.tf32.f32 %0, %1;" : "=r"(r) : "f"(f));
    return r;
}

__device__ __forceinline__ void mma_tf32(float* d, const uint32_t* a, const uint32_t* b) {
    asm volatile(
        "mma.sync.aligned.m16n8k8.row.col.f32.tf32.tf32.f32 "
        "{%0,%1,%2,%3}, {%4,%5,%6,%7}, {%8,%9}, {%0,%1,%2,%3};"
        : "+f"(d[0]), "+f"(d[1]), "+f"(d[2]), "+f"(d[3])
        : "r"(a[0]), "r"(a[1]), "r"(a[2]), "r"(a[3]), "r"(b[0]), "r"(b[1]));
}

// ===========================================================================
// TF32 GEMM v3 (unchanged from R7): C[m][n] = sum_k A[m][k]*W[n][k]
// CTA tile 128x256, BK=32, 8 warps (2m x 4n), warp tile 64x64.
// ===========================================================================
#define LDP2  36
#define A_TW  (128*LDP2)
#define B_TW  (256*LDP2)
#define GEMM_SMEM ((A_TW + B_TW) * 2 * 4)   /* 110592 B */

template<bool DO_CLIP>
__global__ __launch_bounds__(256)
void gemm_mma(const float* __restrict__ A, const float* __restrict__ W,
              float* __restrict__ C, int Ntot, int K) {
    extern __shared__ uint32_t sm[];
    uint32_t* As[2] = { sm,        sm + A_TW + B_TW };
    uint32_t* Bs[2] = { sm + A_TW, sm + 2*A_TW + B_TW };

    const int tid  = threadIdx.x;
    const int lane = tid & 31;
    const int warp = tid >> 5;
    const int wm0  = (warp >> 2) << 6;
    const int wn0  = (warp & 3) << 6;
    const int m0 = blockIdx.y << 7, n0 = blockIdx.x << 8;

    const float* Ab = A + (size_t)m0 * K;
    const float* Wb = W + (size_t)n0 * K;

    const int arow = tid >> 3;
    const int ac4  = tid & 7;

    float acc[4][8][4];
#pragma unroll
    for (int a = 0; a < 4; a++)
#pragma unroll
        for (int b = 0; b < 8; b++)
#pragma unroll
            for (int c = 0; c < 4; c++) acc[a][b][c] = 0.f;

    const int NS = K >> 5;
    float4 pa[4], pb[8];

#pragma unroll
    for (int i = 0; i < 4; i++)
        pa[i] = *(const float4*)(Ab + (size_t)(arow + 32*i) * K + ac4*4);
#pragma unroll
    for (int i = 0; i < 8; i++)
        pb[i] = *(const float4*)(Wb + (size_t)(arow + 32*i) * K + ac4*4);
#pragma unroll
    for (int i = 0; i < 4; i++) {
        uint32_t* p = As[0] + (arow + 32*i) * LDP2 + ac4*4;
        p[0] = f2tf(pa[i].x); p[1] = f2tf(pa[i].y);
        p[2] = f2tf(pa[i].z); p[3] = f2tf(pa[i].w);
    }
#pragma unroll
    for (int i = 0; i < 8; i++) {
        uint32_t* p = Bs[0] + (arow + 32*i) * LDP2 + ac4*4;
        p[0] = f2tf(pb[i].x); p[1] = f2tf(pb[i].y);
        p[2] = f2tf(pb[i].z); p[3] = f2tf(pb[i].w);
    }
    __syncthreads();

    for (int s = 0; s < NS; s++) {
        if (s + 1 < NS) {
            const int k0 = (s + 1) << 5;
#pragma unroll
            for (int i = 0; i < 4; i++)
                pa[i] = *(const float4*)(Ab + (size_t)(arow + 32*i) * K + k0 + ac4*4);
#pragma unroll
            for (int i = 0; i < 8; i++)
                pb[i] = *(const float4*)(Wb + (size_t)(arow + 32*i) * K + k0 + ac4*4);
        }

        const uint32_t* Ac = As[s & 1];
        const uint32_t* Bc = Bs[s & 1];
#pragma unroll
        for (int kk = 0; kk < 4; kk++) {
            const int c = (kk << 3) + (lane & 3);
            uint32_t af[4][4], bf[8][2];
#pragma unroll
            for (int mt = 0; mt < 4; mt++) {
                int r = wm0 + (mt << 4) + (lane >> 2);
                af[mt][0] = Ac[r * LDP2 + c];
                af[mt][1] = Ac[(r + 8) * LDP2 + c];
                af[mt][2] = Ac[r * LDP2 + c + 4];
                af[mt][3] = Ac[(r + 8) * LDP2 + c + 4];
            }
#pragma unroll
            for (int nt = 0; nt < 8; nt++) {
                int n = wn0 + (nt << 3) + (lane >> 2);
                bf[nt][0] = Bc[n * LDP2 + c];
                bf[nt][1] = Bc[n * LDP2 + c + 4];
            }
#pragma unroll
            for (int mt = 0; mt < 4; mt++)
#pragma unroll
                for (int nt = 0; nt < 8; nt++)
                    mma_tf32(acc[mt][nt], af[mt], bf[nt]);
        }

        if (s + 1 < NS) {
            uint32_t* Ad = As[(s + 1) & 1];
            uint32_t* Bd = Bs[(s + 1) & 1];
#pragma unroll
            for (int i = 0; i < 4; i++) {
                uint32_t* p = Ad + (arow + 32*i) * LDP2 + ac4*4;
                p[0] = f2tf(pa[i].x); p[1] = f2tf(pa[i].y);
                p[2] = f2tf(pa[i].z); p[3] = f2tf(pa[i].w);
            }
#pragma unroll
            for (int i = 0; i < 8; i++) {
                uint32_t* p = Bd + (arow + 32*i) * LDP2 + ac4*4;
                p[0] = f2tf(pb[i].x); p[1] = f2tf(pb[i].y);
                p[2] = f2tf(pb[i].z); p[3] = f2tf(pb[i].w);
            }
            __syncthreads();
        }
    }

#pragma unroll
    for (int mt = 0; mt < 4; mt++) {
#pragma unroll
        for (int nt = 0; nt < 8; nt++) {
            int row = m0 + wm0 + (mt << 4) + (lane >> 2);
            int col = n0 + wn0 + (nt << 3) + ((lane & 3) << 1);
            float2 v0 = make_float2(acc[mt][nt][0], acc[mt][nt][1]);
            float2 v1 = make_float2(acc[mt][nt][2], acc[mt][nt][3]);
            if (DO_CLIP) {
                v0.x = fminf(fmaxf(v0.x, -CLIP_V), CLIP_V);
                v0.y = fminf(fmaxf(v0.y, -CLIP_V), CLIP_V);
                v1.x = fminf(fmaxf(v1.x, -CLIP_V), CLIP_V);
                v1.y = fminf(fmaxf(v1.y, -CLIP_V), CLIP_V);
            }
            *(float2*)(C + (size_t)row * Ntot + col) = v0;
            *(float2*)(C + (size_t)(row + 8) * Ntot + col) = v1;
        }
    }
}

// ---------------------------------------------------------------------------
// Fused q/k LayerNorm: grid (ROWS, 2); y=0 -> q slice, y=1 -> k slice.
// ---------------------------------------------------------------------------
__global__ __launch_bounds__(256)
void ln_kernel(float* __restrict__ base,
               const float* __restrict__ wq, const float* __restrict__ bq,
               const float* __restrict__ wk, const float* __restrict__ bk) {
    __shared__ float red0[8], red1[8];
    __shared__ float mu_s, inv_s;
    const float* w = blockIdx.y ? wk : wq;
    const float* b = blockIdx.y ? bk : bq;
    float* x = base + (size_t)blockIdx.x * E3 + blockIdx.y * D_MODEL;
    const int tid = threadIdx.x;

    float s = 0.f, s2 = 0.f;
    for (int i = tid; i < D_MODEL; i += 256) {
        float v = x[i]; s += v; s2 += v * v;
    }
#pragma unroll
    for (int o = 16; o; o >>= 1) {
        s  += __shfl_down_sync(0xffffffffu, s,  o);
        s2 += __shfl_down_sync(0xffffffffu, s2, o);
    }
    if ((tid & 31) == 0) { red0[tid >> 5] = s; red1[tid >> 5] = s2; }
    __syncthreads();
    if (tid == 0) {
        float S = 0.f, S2 = 0.f;
#pragma unroll
        for (int i = 0; i < 8; i++) { S += red0[i]; S2 += red1[i]; }
        float mu = S * (1.f / D_MODEL);
        float var = S2 * (1.f / D_MODEL) - mu * mu;
        mu_s = mu;
        inv_s = rsqrtf(var + LN_EPS);
    }
    __syncthreads();
    const float mu = mu_s, inv = inv_s;
    for (int i = tid; i < D_MODEL; i += 256) {
        x[i] = (x[i] - mu) * inv * w[i] + b[i];
    }
}

// ---------------------------------------------------------------------------
// Flash attention v5: smem diet -> 2 CTAs/SM. m/l state fully in registers
// (every lane holds the reduced row max/sum after the 16-lane shfl tree).
// Qs stride 128, Ks stride 132, Vs 128, Ps stride 64.
// Total smem = 28928 words = 115712 B -> with 1KB/CTA reserve, 2 CTAs = 228KB.
// ---------------------------------------------------------------------------
#define QSTR 128
#define KSTR 132
#define PSTR 64

__global__ __launch_bounds__(256, 2)
void attn_kernel(const float* __restrict__ qkv, float* __restrict__ outp) {
    extern __shared__ float smf[];
    float* Qs = smf;                 // 64*128
    float* Ks = Qs + 64*QSTR;        // 64*132
    float* Vs = Ks + 64*KSTR;        // 64*128
    float* Ps = Vs + 64*128;         // 64*64

    const int qt = blockIdx.x, h = blockIdx.y, b = blockIdx.z;
    const int tid = threadIdx.x;
    const int tx = tid & 15, ty = tid >> 4;
    const float scale = 0.08838834764831845f;            // 1/sqrt(128)
    const float slope = exp2f(-0.25f * (float)(h + 1));  // ALiBi, H == next_p2
    const size_t rowbase = (size_t)b * SEQ;

    // Load + pre-scale Q tile
    for (int i = tid; i < 64 * HDIM / 4; i += 256) {
        int r = i >> 5; int c = (i & 31) << 2;
        float4 v = *(const float4*)(qkv + (rowbase + qt*64 + r) * E3 + h*HDIM + c);
        v.x *= scale; v.y *= scale; v.z *= scale; v.w *= scale;
        *(float4*)(Qs + r*QSTR + c) = v;
    }
    float m_i[4], l_i[4];
    float o[4][8];
#pragma unroll
    for (int i = 0; i < 4; i++) {
        m_i[i] = -1e30f; l_i[i] = 0.f;
#pragma unroll
        for (int c = 0; c < 8; c++) o[i][c] = 0.f;
    }
    __syncthreads();

    for (int kt = 0; kt <= qt; kt++) {
        // Load K (stride 132) and V tiles
        for (int i = tid; i < 64 * HDIM / 4; i += 256) {
            int r = i >> 5; int c = (i & 31) << 2;
            const float* kp = qkv + (rowbase + kt*64 + r) * E3 + D_MODEL + h*HDIM + c;
            *(float4*)(Ks + r*KSTR + c) = *(const float4*)kp;
            *(float4*)(Vs + r*HDIM + c) = *(const float4*)(kp + D_MODEL);
        }
        __syncthreads();

        // S = (Q*scale) K^T
        float sacc[4][4] = {};
#pragma unroll 4
        for (int kb = 0; kb < HDIM; kb += 4) {
            float4 a4[4], b4[4];
#pragma unroll
            for (int i = 0; i < 4; i++)
                a4[i] = *(const float4*)(Qs + (ty*4+i)*QSTR + kb);
#pragma unroll
            for (int j = 0; j < 4; j++)
                b4[j] = *(const float4*)(Ks + (tx + 16*j)*KSTR + kb);
#pragma unroll
            for (int i = 0; i < 4; i++)
#pragma unroll
                for (int j = 0; j < 4; j++) {
                    sacc[i][j] = fmaf(a4[i].x, b4[j].x, sacc[i][j]);
                    sacc[i][j] = fmaf(a4[i].y, b4[j].y, sacc[i][j]);
                    sacc[i][j] = fmaf(a4[i].z, b4[j].z, sacc[i][j]);
                    sacc[i][j] = fmaf(a4[i].w, b4[j].w, sacc[i][j]);
                }
        }

        // Bias + mask + online softmax (registers + 16-lane shfl reductions)
        const int qb = qt*64 + ty*4, kb0 = kt*64;
        float r_[4];
#pragma unroll
        for (int i = 0; i < 4; i++) {
            const int row = ty*4 + i;
            const int qi  = qb + i;
            float v[4];
#pragma unroll
            for (int j = 0; j < 4; j++) {
                int kj = kb0 + tx + 16*j;
                float s = sacc[i][j] + slope * (float)(kj - qi);
                v[j] = (kj > qi) ? -1e30f : s;
            }
            float mx = fmaxf(fmaxf(v[0], v[1]), fmaxf(v[2], v[3]));
            mx = fmaxf(mx, __shfl_xor_sync(0xffffffffu, mx, 1));
            mx = fmaxf(mx, __shfl_xor_sync(0xffffffffu, mx, 2));
            mx = fmaxf(mx, __shfl_xor_sync(0xffffffffu, mx, 4));
            mx = fmaxf(mx, __shfl_xor_sync(0xffffffffu, mx, 8));
            float mn = fmaxf(mx, m_i[i]);
#pragma unroll
            for (int j = 0; j < 4; j++) v[j] = __expf(v[j] - mn);
            float sum = (v[0] + v[1]) + (v[2] + v[3]);
            sum += __shfl_xor_sync(0xffffffffu, sum, 1);
            sum += __shfl_xor_sync(0xffffffffu, sum, 2);
            sum += __shfl_xor_sync(0xffffffffu, sum, 4);
            sum += __shfl_xor_sync(0xffffffffu, sum, 8);
            r_[i] = __expf(m_i[i] - mn);
            m_i[i] = mn;
            l_i[i] = l_i[i] * r_[i] + sum;
            float* prow = Ps + row*PSTR;
#pragma unroll
            for (int j = 0; j < 4; j++) prow[tx + 16*j] = v[j];
        }
        __syncwarp();   // P rows produced & consumed by the same half-warp

        // Rescale O, accumulate P@V
#pragma unroll
        for (int i = 0; i < 4; i++)
#pragma unroll
            for (int c = 0; c < 8; c++) o[i][c] *= r_[i];
#pragma unroll 2
        for (int kb2 = 0; kb2 < 64; kb2 += 4) {
            float pv[4][4];
#pragma unroll
            for (int i = 0; i < 4; i++) {
                float4 p = *(const float4*)(Ps + (ty*4+i)*PSTR + kb2);
                pv[i][0] = p.x; pv[i][1] = p.y; pv[i][2] = p.z; pv[i][3] = p.w;
            }
#pragma unroll
            for (int t = 0; t < 4; t++) {
                float4 v0 = *(const float4*)(Vs + (kb2+t)*HDIM + tx*8);
                float4 v1 = *(const float4*)(Vs + (kb2+t)*HDIM + tx*8 + 4);
#pragma unroll
                for (int i = 0; i < 4; i++) {
                    float p = pv[i][t];
                    o[i][0] = fmaf(p, v0.x, o[i][0]);
                    o[i][1] = fmaf(p, v0.y, o[i][1]);
                    o[i][2] = fmaf(p, v0.z, o[i][2]);
                    o[i][3] = fmaf(p, v0.w, o[i][3]);
                    o[i][4] = fmaf(p, v1.x, o[i][4]);
                    o[i][5] = fmaf(p, v1.y, o[i][5]);
                    o[i][6] = fmaf(p, v1.z, o[i][6]);
                    o[i][7] = fmaf(p, v1.w, o[i][7]);
                }
            }
        }
        __syncthreads();   // protect Ks/Vs before next tile's load
    }

    // Normalize and write
#pragma unroll
    for (int i = 0; i < 4; i++) {
        float inv = 1.f / l_i[i];
        float* op = outp + (rowbase + qt*64 + ty*4 + i) * (size_t)D_MODEL + h*HDIM + tx*8;
        float4 w0 = make_float4(o[i][0]*inv, o[i][1]*inv, o[i][2]*inv, o[i][3]*inv);
        float4 w1 = make_float4(o[i][4]*inv, o[i][5]*inv, o[i][6]*inv, o[i][7]*inv);
        *(float4*)op = w0;
        *(float4*)(op + 4) = w1;
    }
}

#define ATTN_SMEM ((64*QSTR + 64*KSTR + 64*128 + 64*PSTR) * (int)sizeof(float))

// ---------------------------------------------------------------------------
extern "C" void kernel_launch(void* const* d_in, const int* in_sizes, int n_in,
                              void* d_out, int out_size) {
    const float* hidden = (const float*)d_in[0];
    const float* w_qkv  = (const float*)d_in[1];
    const float* q_ln_w = (const float*)d_in[2];
    const float* q_ln_b = (const float*)d_in[3];
    const float* k_ln_w = (const float*)d_in[4];
    const float* k_ln_b = (const float*)d_in[5];
    const float* w_out  = (const float*)d_in[6];
    float* out = (float*)d_out;

    float *qkv, *attn;
    cudaGetSymbolAddress((void**)&qkv, g_qkv);
    cudaGetSymbolAddress((void**)&attn, g_attn);

    cudaFuncSetAttribute(gemm_mma<true>,  cudaFuncAttributeMaxDynamicSharedMemorySize, GEMM_SMEM);
    cudaFuncSetAttribute(gemm_mma<false>, cudaFuncAttributeMaxDynamicSharedMemorySize, GEMM_SMEM);
    cudaFuncSetAttribute(attn_kernel, cudaFuncAttributeMaxDynamicSharedMemorySize, ATTN_SMEM);

    // 1) QKV projection + clip (tf32, 128x256 tiles, BK=32)
    dim3 g1(E3 / 256, ROWS / 128);
    gemm_mma<true><<<g1, 256, GEMM_SMEM>>>(hidden, w_qkv, qkv, E3, D_MODEL);

    // 2) fused q/k LayerNorms
    dim3 gl(ROWS, 2);
    ln_kernel<<<gl, 256>>>(qkv, q_ln_w, q_ln_b, k_ln_w, k_ln_b);

    // 3) Flash attention (2 CTAs/SM)
    dim3 ga(SEQ / 64, NHEADS, BATCH);
    attn_kernel<<<ga, 256, ATTN_SMEM>>>(qkv, attn);

    // 4) Output projection -> d_out (tf32, 128x256 tiles, BK=32)
    dim3 g2(D_MODEL / 256, ROWS / 128);
    gemm_mma<false><<<g2, 256, GEMM_SMEM>>>(attn, w_out, out, D_MODEL, D_MODEL);
}

// round 9
// speedup vs baseline: 1.7049x; 1.1034x over previous
#include <cuda_runtime.h>
#include <cstdint>

#define D_MODEL 4096
#define E3      12288
#define NHEADS  32
#define HDIM    128
#define BATCH   2
#define SEQ     2048
#define ROWS    (BATCH*SEQ)   /* 4096 */
#define CLIP_V  8.0f
#define LN_EPS  1e-5f

// Scratch (allocation-free rule: __device__ globals)
__device__ float g_qkv[(size_t)ROWS * E3];       // [4096][12288] post-GEMM1 (q|k|v)
__device__ float g_attn[(size_t)ROWS * D_MODEL]; // [4096][4096]  attention output

// ===========================================================================
// mma.sync tf32 + cp.async helpers (sm_80+)
// ===========================================================================
__device__ __forceinline__ uint32_t f2tf(float f) {
    uint32_t r;
    asm("cvt.rna.tf32.f32 %0, %1;" : "=r"(r) : "f"(f));
    return r;
}
__device__ __forceinline__ uint32_t u2tf(uint32_t u) {
    return f2tf(__uint_as_float(u));
}

__device__ __forceinline__ void mma_tf32(float* d, const uint32_t* a, const uint32_t* b) {
    asm volatile(
        "mma.sync.aligned.m16n8k8.row.col.f32.tf32.tf32.f32 "
        "{%0,%1,%2,%3}, {%4,%5,%6,%7}, {%8,%9}, {%0,%1,%2,%3};"
        : "+f"(d[0]), "+f"(d[1]), "+f"(d[2]), "+f"(d[3])
        : "r"(a[0]), "r"(a[1]), "r"(a[2]), "r"(a[3]), "r"(b[0]), "r"(b[1]));
}

__device__ __forceinline__ void cp16(uint32_t saddr, const float* g) {
    asm volatile("cp.async.cg.shared.global [%0], [%1], 16;"
                 :: "r"(saddr), "l"(g) : "memory");
}
#define CP_COMMIT()  asm volatile("cp.async.commit_group;" ::: "memory")
#define CP_WAIT1()   asm volatile("cp.async.wait_group 1;" ::: "memory")

// ===========================================================================
// TF32 GEMM v4: C[m][n] = sum_k A[m][k]*W[n][k]
// CTA tile 128x256, BK=32, 8 warps (2m x 4n), warp tile 64x64.
// cp.async 3-stage pipeline; smem holds raw fp32; tf32 cvt at fragment load.
// grid = (Ntot/256, M/128), 256 threads.
// ===========================================================================
#define LDP2  36
#define A_TW  (128*LDP2)          /* 4608 words */
#define B_TW  (256*LDP2)          /* 9216 words */
#define STG_W (A_TW + B_TW)       /* 13824 words per stage */
#define GEMM_SMEM (STG_W * 3 * 4) /* 165888 B */

template<bool DO_CLIP>
__global__ __launch_bounds__(256)
void gemm_mma(const float* __restrict__ A, const float* __restrict__ W,
              float* __restrict__ C, int Ntot, int K) {
    extern __shared__ uint32_t sm[];

    const int tid  = threadIdx.x;
    const int lane = tid & 31;
    const int warp = tid >> 5;
    const int wm0  = (warp >> 2) << 6;   // 0 or 64
    const int wn0  = (warp & 3) << 6;    // 0,64,128,192
    const int m0 = blockIdx.y << 7, n0 = blockIdx.x << 8;

    const float* Ab = A + (size_t)m0 * K;
    const float* Wb = W + (size_t)n0 * K;

    const int arow = tid >> 3;           // 0..31
    const int ac4  = tid & 7;            // float4 group in BK=32

    const uint32_t sbase = (uint32_t)__cvta_generic_to_shared(sm);
    // per-thread smem byte offsets within a stage (A: 4 lines, B: 8 lines)
    const uint32_t soffA = ((uint32_t)(arow * LDP2 + ac4 * 4)) * 4;
    const uint32_t sstrA = (uint32_t)(32 * LDP2) * 4;

    float acc[4][8][4];
#pragma unroll
    for (int a = 0; a < 4; a++)
#pragma unroll
        for (int b = 0; b < 8; b++)
#pragma unroll
            for (int c = 0; c < 4; c++) acc[a][b][c] = 0.f;

    const int NS = K >> 5;

#define ISSUE_STAGE(buf, k0)                                                      \
    do {                                                                          \
        uint32_t _sa = sbase + (uint32_t)(buf) * (STG_W * 4) + soffA;             \
        uint32_t _sb = _sa + (uint32_t)(A_TW * 4);                                \
        _Pragma("unroll")                                                         \
        for (int _i = 0; _i < 4; _i++)                                            \
            cp16(_sa + _i * sstrA,                                                \
                 Ab + (size_t)(arow + 32*_i) * K + (k0) + ac4*4);                 \
        _Pragma("unroll")                                                         \
        for (int _i = 0; _i < 8; _i++)                                            \
            cp16(_sb + _i * sstrA,                                                \
                 Wb + (size_t)(arow + 32*_i) * K + (k0) + ac4*4);                 \
        CP_COMMIT();                                                              \
    } while (0)

    ISSUE_STAGE(0, 0);
    ISSUE_STAGE(1, 32);

    int cur = 0, nxt = 2;   // compute buffer, next-issue buffer
    for (int s = 0; s < NS; s++) {
        CP_WAIT1();            // stage s landed (<=1 group outstanding)
        __syncthreads();       // visible to all; also: all warps done with buf 'nxt'
        if (s + 2 < NS) ISSUE_STAGE(nxt, (s + 2) << 5);

        const uint32_t* Ac = sm + cur * STG_W;
        const uint32_t* Bc = Ac + A_TW;
#pragma unroll
        for (int kk = 0; kk < 4; kk++) {
            const int c = (kk << 3) + (lane & 3);
            uint32_t af[4][4], bf[8][2];
#pragma unroll
            for (int mt = 0; mt < 4; mt++) {
                int r = wm0 + (mt << 4) + (lane >> 2);
                af[mt][0] = u2tf(Ac[r * LDP2 + c]);
                af[mt][1] = u2tf(Ac[(r + 8) * LDP2 + c]);
                af[mt][2] = u2tf(Ac[r * LDP2 + c + 4]);
                af[mt][3] = u2tf(Ac[(r + 8) * LDP2 + c + 4]);
            }
#pragma unroll
            for (int nt = 0; nt < 8; nt++) {
                int n = wn0 + (nt << 3) + (lane >> 2);
                bf[nt][0] = u2tf(Bc[n * LDP2 + c]);
                bf[nt][1] = u2tf(Bc[n * LDP2 + c + 4]);
            }
#pragma unroll
            for (int mt = 0; mt < 4; mt++)
#pragma unroll
                for (int nt = 0; nt < 8; nt++)
                    mma_tf32(acc[mt][nt], af[mt], bf[nt]);
        }

        cur = (cur == 2) ? 0 : cur + 1;
        nxt = (nxt == 2) ? 0 : nxt + 1;
    }
#undef ISSUE_STAGE

    // epilogue
#pragma unroll
    for (int mt = 0; mt < 4; mt++) {
#pragma unroll
        for (int nt = 0; nt < 8; nt++) {
            int row = m0 + wm0 + (mt << 4) + (lane >> 2);
            int col = n0 + wn0 + (nt << 3) + ((lane & 3) << 1);
            float2 v0 = make_float2(acc[mt][nt][0], acc[mt][nt][1]);
            float2 v1 = make_float2(acc[mt][nt][2], acc[mt][nt][3]);
            if (DO_CLIP) {
                v0.x = fminf(fmaxf(v0.x, -CLIP_V), CLIP_V);
                v0.y = fminf(fmaxf(v0.y, -CLIP_V), CLIP_V);
                v1.x = fminf(fmaxf(v1.x, -CLIP_V), CLIP_V);
                v1.y = fminf(fmaxf(v1.y, -CLIP_V), CLIP_V);
            }
            *(float2*)(C + (size_t)row * Ntot + col) = v0;
            *(float2*)(C + (size_t)(row + 8) * Ntot + col) = v1;
        }
    }
}

// ---------------------------------------------------------------------------
// Fused q/k LayerNorm (unchanged from R8)
// ---------------------------------------------------------------------------
__global__ __launch_bounds__(256)
void ln_kernel(float* __restrict__ base,
               const float* __restrict__ wq, const float* __restrict__ bq,
               const float* __restrict__ wk, const float* __restrict__ bk) {
    __shared__ float red0[8], red1[8];
    __shared__ float mu_s, inv_s;
    const float* w = blockIdx.y ? wk : wq;
    const float* b = blockIdx.y ? bk : bq;
    float* x = base + (size_t)blockIdx.x * E3 + blockIdx.y * D_MODEL;
    const int tid = threadIdx.x;

    float s = 0.f, s2 = 0.f;
    for (int i = tid; i < D_MODEL; i += 256) {
        float v = x[i]; s += v; s2 += v * v;
    }
#pragma unroll
    for (int o = 16; o; o >>= 1) {
        s  += __shfl_down_sync(0xffffffffu, s,  o);
        s2 += __shfl_down_sync(0xffffffffu, s2, o);
    }
    if ((tid & 31) == 0) { red0[tid >> 5] = s; red1[tid >> 5] = s2; }
    __syncthreads();
    if (tid == 0) {
        float S = 0.f, S2 = 0.f;
#pragma unroll
        for (int i = 0; i < 8; i++) { S += red0[i]; S2 += red1[i]; }
        float mu = S * (1.f / D_MODEL);
        float var = S2 * (1.f / D_MODEL) - mu * mu;
        mu_s = mu;
        inv_s = rsqrtf(var + LN_EPS);
    }
    __syncthreads();
    const float mu = mu_s, inv = inv_s;
    for (int i = tid; i < D_MODEL; i += 256) {
        x[i] = (x[i] - mu) * inv * w[i] + b[i];
    }
}

// ---------------------------------------------------------------------------
// Flash attention v5 (unchanged from R8): 2 CTAs/SM, register softmax.
// ---------------------------------------------------------------------------
#define QSTR 128
#define KSTR 132
#define PSTR 64

__global__ __launch_bounds__(256, 2)
void attn_kernel(const float* __restrict__ qkv, float* __restrict__ outp) {
    extern __shared__ float smf[];
    float* Qs = smf;                 // 64*128
    float* Ks = Qs + 64*QSTR;        // 64*132
    float* Vs = Ks + 64*KSTR;        // 64*128
    float* Ps = Vs + 64*128;         // 64*64

    const int qt = blockIdx.x, h = blockIdx.y, b = blockIdx.z;
    const int tid = threadIdx.x;
    const int tx = tid & 15, ty = tid >> 4;
    const float scale = 0.08838834764831845f;            // 1/sqrt(128)
    const float slope = exp2f(-0.25f * (float)(h + 1));  // ALiBi, H == next_p2
    const size_t rowbase = (size_t)b * SEQ;

    for (int i = tid; i < 64 * HDIM / 4; i += 256) {
        int r = i >> 5; int c = (i & 31) << 2;
        float4 v = *(const float4*)(qkv + (rowbase + qt*64 + r) * E3 + h*HDIM + c);
        v.x *= scale; v.y *= scale; v.z *= scale; v.w *= scale;
        *(float4*)(Qs + r*QSTR + c) = v;
    }
    float m_i[4], l_i[4];
    float o[4][8];
#pragma unroll
    for (int i = 0; i < 4; i++) {
        m_i[i] = -1e30f; l_i[i] = 0.f;
#pragma unroll
        for (int c = 0; c < 8; c++) o[i][c] = 0.f;
    }
    __syncthreads();

    for (int kt = 0; kt <= qt; kt++) {
        for (int i = tid; i < 64 * HDIM / 4; i += 256) {
            int r = i >> 5; int c = (i & 31) << 2;
            const float* kp = qkv + (rowbase + kt*64 + r) * E3 + D_MODEL + h*HDIM + c;
            *(float4*)(Ks + r*KSTR + c) = *(const float4*)kp;
            *(float4*)(Vs + r*HDIM + c) = *(const float4*)(kp + D_MODEL);
        }
        __syncthreads();

        float sacc[4][4] = {};
#pragma unroll 4
        for (int kb = 0; kb < HDIM; kb += 4) {
            float4 a4[4], b4[4];
#pragma unroll
            for (int i = 0; i < 4; i++)
                a4[i] = *(const float4*)(Qs + (ty*4+i)*QSTR + kb);
#pragma unroll
            for (int j = 0; j < 4; j++)
                b4[j] = *(const float4*)(Ks + (tx + 16*j)*KSTR + kb);
#pragma unroll
            for (int i = 0; i < 4; i++)
#pragma unroll
                for (int j = 0; j < 4; j++) {
                    sacc[i][j] = fmaf(a4[i].x, b4[j].x, sacc[i][j]);
                    sacc[i][j] = fmaf(a4[i].y, b4[j].y, sacc[i][j]);
                    sacc[i][j] = fmaf(a4[i].z, b4[j].z, sacc[i][j]);
                    sacc[i][j] = fmaf(a4[i].w, b4[j].w, sacc[i][j]);
                }
        }

        const int qb = qt*64 + ty*4, kb0 = kt*64;
        float r_[4];
#pragma unroll
        for (int i = 0; i < 4; i++) {
            const int row = ty*4 + i;
            const int qi  = qb + i;
            float v[4];
#pragma unroll
            for (int j = 0; j < 4; j++) {
                int kj = kb0 + tx + 16*j;
                float s = sacc[i][j] + slope * (float)(kj - qi);
                v[j] = (kj > qi) ? -1e30f : s;
            }
            float mx = fmaxf(fmaxf(v[0], v[1]), fmaxf(v[2], v[3]));
            mx = fmaxf(mx, __shfl_xor_sync(0xffffffffu, mx, 1));
            mx = fmaxf(mx, __shfl_xor_sync(0xffffffffu, mx, 2));
            mx = fmaxf(mx, __shfl_xor_sync(0xffffffffu, mx, 4));
            mx = fmaxf(mx, __shfl_xor_sync(0xffffffffu, mx, 8));
            float mn = fmaxf(mx, m_i[i]);
#pragma unroll
            for (int j = 0; j < 4; j++) v[j] = __expf(v[j] - mn);
            float sum = (v[0] + v[1]) + (v[2] + v[3]);
            sum += __shfl_xor_sync(0xffffffffu, sum, 1);
            sum += __shfl_xor_sync(0xffffffffu, sum, 2);
            sum += __shfl_xor_sync(0xffffffffu, sum, 4);
            sum += __shfl_xor_sync(0xffffffffu, sum, 8);
            r_[i] = __expf(m_i[i] - mn);
            m_i[i] = mn;
            l_i[i] = l_i[i] * r_[i] + sum;
            float* prow = Ps + row*PSTR;
#pragma unroll
            for (int j = 0; j < 4; j++) prow[tx + 16*j] = v[j];
        }
        __syncwarp();

#pragma unroll
        for (int i = 0; i < 4; i++)
#pragma unroll
            for (int c = 0; c < 8; c++) o[i][c] *= r_[i];
#pragma unroll 2
        for (int kb2 = 0; kb2 < 64; kb2 += 4) {
            float pv[4][4];
#pragma unroll
            for (int i = 0; i < 4; i++) {
                float4 p = *(const float4*)(Ps + (ty*4+i)*PSTR + kb2);
                pv[i][0] = p.x; pv[i][1] = p.y; pv[i][2] = p.z; pv[i][3] = p.w;
            }
#pragma unroll
            for (int t = 0; t < 4; t++) {
                float4 v0 = *(const float4*)(Vs + (kb2+t)*HDIM + tx*8);
                float4 v1 = *(const float4*)(Vs + (kb2+t)*HDIM + tx*8 + 4);
#pragma unroll
                for (int i = 0; i < 4; i++) {
                    float p = pv[i][t];
                    o[i][0] = fmaf(p, v0.x, o[i][0]);
                    o[i][1] = fmaf(p, v0.y, o[i][1]);
                    o[i][2] = fmaf(p, v0.z, o[i][2]);
                    o[i][3] = fmaf(p, v0.w, o[i][3]);
                    o[i][4] = fmaf(p, v1.x, o[i][4]);
                    o[i][5] = fmaf(p, v1.y, o[i][5]);
                    o[i][6] = fmaf(p, v1.z, o[i][6]);
                    o[i][7] = fmaf(p, v1.w, o[i][7]);
                }
            }
        }
        __syncthreads();
    }

#pragma unroll
    for (int i = 0; i < 4; i++) {
        float inv = 1.f / l_i[i];
        float* op = outp + (rowbase + qt*64 + ty*4 + i) * (size_t)D_MODEL + h*HDIM + tx*8;
        float4 w0 = make_float4(o[i][0]*inv, o[i][1]*inv, o[i][2]*inv, o[i][3]*inv);
        float4 w1 = make_float4(o[i][4]*inv, o[i][5]*inv, o[i][6]*inv, o[i][7]*inv);
        *(float4*)op = w0;
        *(float4*)(op + 4) = w1;
    }
}

#define ATTN_SMEM ((64*QSTR + 64*KSTR + 64*128 + 64*PSTR) * (int)sizeof(float))

// ---------------------------------------------------------------------------
extern "C" void kernel_launch(void* const* d_in, const int* in_sizes, int n_in,
                              void* d_out, int out_size) {
    const float* hidden = (const float*)d_in[0];
    const float* w_qkv  = (const float*)d_in[1];
    const float* q_ln_w = (const float*)d_in[2];
    const float* q_ln_b = (const float*)d_in[3];
    const float* k_ln_w = (const float*)d_in[4];
    const float* k_ln_b = (const float*)d_in[5];
    const float* w_out  = (const float*)d_in[6];
    float* out = (float*)d_out;

    float *qkv, *attn;
    cudaGetSymbolAddress((void**)&qkv, g_qkv);
    cudaGetSymbolAddress((void**)&attn, g_attn);

    cudaFuncSetAttribute(gemm_mma<true>,  cudaFuncAttributeMaxDynamicSharedMemorySize, GEMM_SMEM);
    cudaFuncSetAttribute(gemm_mma<false>, cudaFuncAttributeMaxDynamicSharedMemorySize, GEMM_SMEM);
    cudaFuncSetAttribute(attn_kernel, cudaFuncAttributeMaxDynamicSharedMemorySize, ATTN_SMEM);

    // 1) QKV projection + clip (tf32, cp.async 3-stage)
    dim3 g1(E3 / 256, ROWS / 128);
    gemm_mma<true><<<g1, 256, GEMM_SMEM>>>(hidden, w_qkv, qkv, E3, D_MODEL);

    // 2) fused q/k LayerNorms
    dim3 gl(ROWS, 2);
    ln_kernel<<<gl, 256>>>(qkv, q_ln_w, q_ln_b, k_ln_w, k_ln_b);

    // 3) Flash attention (2 CTAs/SM)
    dim3 ga(SEQ / 64, NHEADS, BATCH);
    attn_kernel<<<ga, 256, ATTN_SMEM>>>(qkv, attn);

    // 4) Output projection -> d_out (tf32, cp.async 3-stage)
    dim3 g2(D_MODEL / 256, ROWS / 128);
    gemm_mma<false><<<g2, 256, GEMM_SMEM>>>(attn, w_out, out, D_MODEL, D_MODEL);
}